// round 2
// baseline (speedup 1.0000x reference)
#include <cuda_runtime.h>

#define N_NODES 50000
#define N_EDGES 600000
#define D 128
#define NGRAPH 64
#define DOUT 16

// ---------------- scratch (device globals: no allocation allowed) -------------
__device__ __align__(128) float g_agg[N_NODES * D];
__device__ __align__(128) float g_h1[N_NODES * D];
__device__ __align__(128) float g_h2[N_NODES * D];
__device__ __align__(128) float g_wt[3][256 * D];   // [k][o] pre-transposed [W_l|W_r]
__device__ __align__(128) float g_gsum[NGRAPH * D];
__device__ float g_inv[N_NODES];
__device__ float g_cnt[N_NODES];
__device__ float g_gcnt[NGRAPH];
__device__ int   g_src[N_EDGES];
__device__ int   g_dst[N_EDGES];

// ---------------- tiny prep kernels -----------------------------------------
__global__ void zero_small() {
    int i = blockIdx.x * blockDim.x + threadIdx.x;
    if (i < N_NODES) g_cnt[i] = 0.f;
    if (i < NGRAPH * D) g_gsum[i] = 0.f;
    if (i < NGRAPH) g_gcnt[i] = 0.f;
}

__global__ void zero_agg() {
    int i = blockIdx.x * blockDim.x + threadIdx.x;   // exactly N_NODES*D/4 threads
    ((float4*)g_agg)[i] = make_float4(0.f, 0.f, 0.f, 0.f);
}

// edge_index is int32 (JAX x64 disabled demotes jnp.int64 -> int32)
__global__ void prep_edges(const int* __restrict__ ei) {
    int e = blockIdx.x * blockDim.x + threadIdx.x;
    if (e >= N_EDGES) return;
    int s = ei[e];
    int d = ei[N_EDGES + e];
    s = min(max(s, 0), N_NODES - 1);
    d = min(max(d, 0), N_NODES - 1);
    g_src[e] = s;
    g_dst[e] = d;
    atomicAdd(&g_cnt[d], 1.f);
}

__global__ void prep_nodes(const int* __restrict__ batch) {
    int n = blockIdx.x * blockDim.x + threadIdx.x;
    if (n >= N_NODES) return;
    g_inv[n] = 1.f / fmaxf(g_cnt[n], 1.f);
    int g = min(max(batch[n], 0), NGRAPH - 1);
    atomicAdd(&g_gcnt[g], 1.f);
}

// Wt[k][o]: k<128 -> W_l[o][k], k>=128 -> W_r[o][k-128]
__global__ void build_wt(const float* __restrict__ wl, const float* __restrict__ wr, int layer) {
    int i = blockIdx.x * blockDim.x + threadIdx.x;   // 256*128 threads
    int k = i >> 7, o = i & 127;
    g_wt[layer][i] = (k < 128) ? wl[o * 128 + k] : wr[o * 128 + (k - 128)];
}

// ---------------- edge aggregation (scatter-add) -----------------------------
__device__ __forceinline__ void red_add_v4(float* p, float4 v) {
    asm volatile("red.global.add.v4.f32 [%0], {%1,%2,%3,%4};"
                 :: "l"(p), "f"(v.x), "f"(v.y), "f"(v.z), "f"(v.w) : "memory");
}

// one warp per edge; lane l moves channels [4l, 4l+4)
__global__ void aggregate(const float* __restrict__ x, int sel) {
    int t = blockIdx.x * blockDim.x + threadIdx.x;
    int e = t >> 5, lane = t & 31;
    if (e >= N_EDGES) return;
    const float* src = (sel == 0) ? x : (sel == 1 ? g_h1 : g_h2);
    int s = g_src[e], d = g_dst[e];
    float4 v = ((const float4*)(src + s * D))[lane];
    red_add_v4(g_agg + d * D + lane * 4, v);
}

// ---------------- fused SAGE-layer GEMM --------------------------------------
// Y[m, o] = relu( sum_{k<128} (agg[m,k]*inv[m]) * Wl[o,k]
//               + sum_{k<128} hin[m,k]          * Wr[o,k] + b[o] )
// as a single M x 128 x 256 GEMM against pre-transposed g_wt[layer].
// CTA tile 128x128, 256 threads, 8x8 microtile, BK=16, double buffered.
__global__ __launch_bounds__(256) void gemm(const float* __restrict__ xin,
                                            int in_sel, int out_sel, int layer,
                                            const float* __restrict__ bias) {
    __shared__ __align__(16) float sA[2][16 * 128];  // [k][m]
    __shared__ __align__(16) float sB[2][16 * 128];  // [k][o]

    const float* hin = (in_sel == 0) ? xin : (in_sel == 1 ? g_h1 : g_h2);
    float* hout = (out_sel == 1) ? g_h1 : g_h2;
    const float* wt = g_wt[layer];

    int tid = threadIdx.x;
    int tx = tid & 15, ty = tid >> 4;
    int m0 = blockIdx.x * 128;

    float acc[8][8];
#pragma unroll
    for (int i = 0; i < 8; i++)
#pragma unroll
        for (int j = 0; j < 8; j++) acc[i][j] = 0.f;

    float4 pa0, pa1, pb0, pb1;

    auto fetchA = [&](int c, float4& r0, float4& r1) {
        const float* A = (c < 8) ? g_agg : hin;
        int kbase = (c < 8) ? c * 16 : c * 16 - 128;
#pragma unroll
        for (int r = 0; r < 2; r++) {
            int f = tid + r * 256;
            int row = f >> 2, kq = f & 3;
            int m = m0 + row;
            float4 v = make_float4(0.f, 0.f, 0.f, 0.f);
            if (m < N_NODES) {
                v = *(const float4*)(A + m * 128 + kbase + kq * 4);
                if (c < 8) {
                    float s = g_inv[m];
                    v.x *= s; v.y *= s; v.z *= s; v.w *= s;
                }
            }
            if (r == 0) r0 = v; else r1 = v;
        }
    };
    auto storeA = [&](int buf, float4 r0, float4 r1) {
#pragma unroll
        for (int r = 0; r < 2; r++) {
            float4 v = r ? r1 : r0;
            int f = tid + r * 256;
            int row = f >> 2, kq = f & 3;
            sA[buf][(kq * 4 + 0) * 128 + row] = v.x;
            sA[buf][(kq * 4 + 1) * 128 + row] = v.y;
            sA[buf][(kq * 4 + 2) * 128 + row] = v.z;
            sA[buf][(kq * 4 + 3) * 128 + row] = v.w;
        }
    };
    // B tile for chunk c is a contiguous 2048-float block of g_wt
    auto fetchB = [&](int c, float4& r0, float4& r1) {
        r0 = *(const float4*)(wt + c * 16 * 128 + tid * 4);
        r1 = *(const float4*)(wt + c * 16 * 128 + (tid + 256) * 4);
    };
    auto storeB = [&](int buf, float4 r0, float4 r1) {
        *(float4*)&sB[buf][tid * 4] = r0;
        *(float4*)&sB[buf][(tid + 256) * 4] = r1;
    };

    fetchA(0, pa0, pa1); fetchB(0, pb0, pb1);
    storeA(0, pa0, pa1); storeB(0, pb0, pb1);
    __syncthreads();

    for (int c = 0; c < 16; c++) {
        int buf = c & 1;
        if (c < 15) { fetchA(c + 1, pa0, pa1); fetchB(c + 1, pb0, pb1); }
#pragma unroll
        for (int kk = 0; kk < 16; kk++) {
            float4 a0 = *(const float4*)&sA[buf][kk * 128 + ty * 8];
            float4 a1 = *(const float4*)&sA[buf][kk * 128 + ty * 8 + 4];
            float4 b0 = *(const float4*)&sB[buf][kk * 128 + tx * 8];
            float4 b1 = *(const float4*)&sB[buf][kk * 128 + tx * 8 + 4];
            float a[8] = {a0.x, a0.y, a0.z, a0.w, a1.x, a1.y, a1.z, a1.w};
            float b[8] = {b0.x, b0.y, b0.z, b0.w, b1.x, b1.y, b1.z, b1.w};
#pragma unroll
            for (int i = 0; i < 8; i++)
#pragma unroll
                for (int j = 0; j < 8; j++) acc[i][j] += a[i] * b[j];
        }
        if (c < 15) { storeA(1 - buf, pa0, pa1); storeB(1 - buf, pb0, pb1); }
        __syncthreads();
    }

    float bj[8];
#pragma unroll
    for (int j = 0; j < 8; j++) bj[j] = bias[tx * 8 + j];
#pragma unroll
    for (int i = 0; i < 8; i++) {
        int m = m0 + ty * 8 + i;
        if (m < N_NODES) {
            float4 o0, o1;
            o0.x = fmaxf(acc[i][0] + bj[0], 0.f);
            o0.y = fmaxf(acc[i][1] + bj[1], 0.f);
            o0.z = fmaxf(acc[i][2] + bj[2], 0.f);
            o0.w = fmaxf(acc[i][3] + bj[3], 0.f);
            o1.x = fmaxf(acc[i][4] + bj[4], 0.f);
            o1.y = fmaxf(acc[i][5] + bj[5], 0.f);
            o1.z = fmaxf(acc[i][6] + bj[6], 0.f);
            o1.w = fmaxf(acc[i][7] + bj[7], 0.f);
            *(float4*)(hout + m * 128 + tx * 8) = o0;
            *(float4*)(hout + m * 128 + tx * 8 + 4) = o1;
        }
    }
}

// ---------------- pool + head ------------------------------------------------
__global__ void pool(const int* __restrict__ batch) {
    int t = blockIdx.x * blockDim.x + threadIdx.x;
    int n = t >> 5, lane = t & 31;
    if (n >= N_NODES) return;
    int g = min(max(batch[n], 0), NGRAPH - 1);
    float4 v = ((const float4*)(g_h1 + n * D))[lane];
    red_add_v4(g_gsum + g * D + lane * 4, v);
}

__global__ void finalk(const float* __restrict__ wlin, const float* __restrict__ blin,
                       float* __restrict__ out) {
    int g = blockIdx.x;
    __shared__ float row[128];
    int t = threadIdx.x;
    float inv = 1.f / fmaxf(g_gcnt[g], 1.f);
    row[t] = g_gsum[g * 128 + t] * inv;
    __syncthreads();
    if (t < DOUT) {
        float acc = blin[t];
#pragma unroll 4
        for (int k = 0; k < 128; k++) acc += row[k] * wlin[t * 128 + k];
        out[g * DOUT + t] = acc;
    }
}

// ---------------- launch -----------------------------------------------------
extern "C" void kernel_launch(void* const* d_in, const int* in_sizes, int n_in,
                              void* d_out, int out_size) {
    const float* x     = (const float*)d_in[0];
    const int*   ei    = (const int*)d_in[1];    // int32: JAX demotes int64 (x64 disabled)
    const int*   batch = (const int*)d_in[2];
    const float* w1l = (const float*)d_in[3];
    const float* b1  = (const float*)d_in[4];
    const float* w1r = (const float*)d_in[5];
    const float* w2l = (const float*)d_in[6];
    const float* b2  = (const float*)d_in[7];
    const float* w2r = (const float*)d_in[8];
    const float* w3l = (const float*)d_in[9];
    const float* b3  = (const float*)d_in[10];
    const float* w3r = (const float*)d_in[11];
    const float* wlin = (const float*)d_in[12];
    const float* blin = (const float*)d_in[13];
    float* out = (float*)d_out;

    zero_small<<<196, 256>>>();
    prep_edges<<<(N_EDGES + 255) / 256, 256>>>(ei);
    prep_nodes<<<(N_NODES + 255) / 256, 256>>>(batch);
    build_wt<<<128, 256>>>(w1l, w1r, 0);
    build_wt<<<128, 256>>>(w2l, w2r, 1);
    build_wt<<<128, 256>>>(w3l, w3r, 2);

    const int AGG_BLOCKS = (N_EDGES * 32) / 256;     // 75000, exact
    const int ZA_BLOCKS  = (N_NODES * D / 4) / 256;  // 6250, exact
    const int GEMM_BLOCKS = (N_NODES + 127) / 128;   // 391

    // layer 1: x -> h1
    zero_agg<<<ZA_BLOCKS, 256>>>();
    aggregate<<<AGG_BLOCKS, 256>>>(x, 0);
    gemm<<<GEMM_BLOCKS, 256>>>(x, 0, 1, 0, b1);
    // layer 2: h1 -> h2
    zero_agg<<<ZA_BLOCKS, 256>>>();
    aggregate<<<AGG_BLOCKS, 256>>>(x, 1);
    gemm<<<GEMM_BLOCKS, 256>>>(x, 1, 2, 1, b2);
    // layer 3: h2 -> h1
    zero_agg<<<ZA_BLOCKS, 256>>>();
    aggregate<<<AGG_BLOCKS, 256>>>(x, 2);
    gemm<<<GEMM_BLOCKS, 256>>>(x, 2, 1, 2, b3);

    pool<<<(N_NODES * 32) / 256, 256>>>(batch);
    finalk<<<NGRAPH, 128>>>(wlin, blin, out);
}

// round 7
// speedup vs baseline: 1.3139x; 1.3139x over previous
#include <cuda_runtime.h>
#include <cuda_bf16.h>
#include <cstdint>

#define N_NODES 50000
#define N_EDGES 600000
#define D 128
#define NGRAPH 64
#define DOUT 16

// ================= device scratch (no allocation allowed) ====================
__device__ __align__(128) float g_agg[N_NODES * D];
__device__ __align__(128) float g_h1[N_NODES * D];
__device__ __align__(128) float g_h2[N_NODES * D];
__device__ float g_inv[N_NODES];
__device__ float g_cnt[N_NODES];
__device__ float g_gcnt[NGRAPH];
__device__ __align__(128) float g_gsum[NGRAPH * D];
__device__ int   g_src[N_EDGES];
__device__ int   g_dst[N_EDGES];
// split-bf16 weight planes: [layer][o=128][k=256], k-contiguous (natural row-major)
__device__ __align__(128) __nv_bfloat16 g_wbh[3 * 32768];
__device__ __align__(128) __nv_bfloat16 g_wbl[3 * 32768];

// ================= helpers ===================================================
__device__ __forceinline__ uint32_t smem_u32(const void* p) {
    uint32_t a;
    asm("{ .reg .u64 t; cvta.to.shared.u64 t, %1; cvt.u32.u64 %0, t; }" : "=r"(a) : "l"(p));
    return a;
}
// pack two floats' bf16-hi parts into one u32; lo residuals into 'lo'
__device__ __forceinline__ uint32_t pack_hi(float a, float b, uint32_t& lo) {
    __nv_bfloat16 ah = __float2bfloat16(a), bh = __float2bfloat16(b);
    __nv_bfloat16 al = __float2bfloat16(a - __bfloat162float(ah));
    __nv_bfloat16 bl = __float2bfloat16(b - __bfloat162float(bh));
    lo = ((uint32_t)__bfloat16_as_ushort(bl) << 16) | __bfloat16_as_ushort(al);
    return ((uint32_t)__bfloat16_as_ushort(bh) << 16) | __bfloat16_as_ushort(ah);
}

#define LDSM_X4(R, A) \
    asm volatile("ldmatrix.sync.aligned.m8n8.x4.shared.b16 {%0,%1,%2,%3}, [%4];" \
                 : "=r"((R)[0]), "=r"((R)[1]), "=r"((R)[2]), "=r"((R)[3]) : "r"(A))
#define LDSM_X2(R, A) \
    asm volatile("ldmatrix.sync.aligned.m8n8.x2.shared.b16 {%0,%1}, [%2];" \
                 : "=r"((R)[0]), "=r"((R)[1]) : "r"(A))
#define MMA_BF16(C, A, B) \
    asm volatile("mma.sync.aligned.m16n8k16.row.col.f32.bf16.bf16.f32 " \
                 "{%0,%1,%2,%3}, {%4,%5,%6,%7}, {%8,%9}, {%0,%1,%2,%3};" \
                 : "+f"((C)[0]), "+f"((C)[1]), "+f"((C)[2]), "+f"((C)[3]) \
                 : "r"((A)[0]), "r"((A)[1]), "r"((A)[2]), "r"((A)[3]), "r"((B)[0]), "r"((B)[1]))

// ================= prep kernels =============================================
__global__ void zero_small() {
    int i = blockIdx.x * blockDim.x + threadIdx.x;
    if (i < N_NODES) g_cnt[i] = 0.f;
    if (i < NGRAPH * D) g_gsum[i] = 0.f;
    if (i < NGRAPH) g_gcnt[i] = 0.f;
}
__global__ void zero_agg() {
    int i = blockIdx.x * blockDim.x + threadIdx.x;
    ((float4*)g_agg)[i] = make_float4(0.f, 0.f, 0.f, 0.f);
}
__global__ void prep_edges(const int* __restrict__ ei) {
    int e = blockIdx.x * blockDim.x + threadIdx.x;
    if (e >= N_EDGES) return;
    int s = min(max(ei[e], 0), N_NODES - 1);
    int d = min(max(ei[N_EDGES + e], 0), N_NODES - 1);
    g_src[e] = s;
    g_dst[e] = d;
    atomicAdd(&g_cnt[d], 1.f);
}
__global__ void prep_nodes(const int* __restrict__ batch) {
    int n = blockIdx.x * blockDim.x + threadIdx.x;
    if (n >= N_NODES) return;
    g_inv[n] = 1.f / fmaxf(g_cnt[n], 1.f);
    atomicAdd(&g_gcnt[min(max(batch[n], 0), NGRAPH - 1)], 1.f);
}
// B[o][k] = Wl[o][k] (k<128) | Wr[o][k-128], split to bf16 hi/lo planes.
__global__ void build_wplanes(const float* __restrict__ wl, const float* __restrict__ wr, int layer) {
    int i = blockIdx.x * blockDim.x + threadIdx.x;   // 4096 threads: o(128) x kgroup(32)
    if (i >= 4096) return;
    int o = i >> 5, k0 = (i & 31) * 8;
    const float* src = (k0 < 128) ? (wl + o * 128 + k0) : (wr + o * 128 + (k0 - 128));
    float4 v0 = ((const float4*)src)[0], v1 = ((const float4*)src)[1];
    uint4 hi, lo;
    hi.x = pack_hi(v0.x, v0.y, lo.x);
    hi.y = pack_hi(v0.z, v0.w, lo.y);
    hi.z = pack_hi(v1.x, v1.y, lo.z);
    hi.w = pack_hi(v1.z, v1.w, lo.w);
    *(uint4*)&g_wbh[layer * 32768 + o * 256 + k0] = hi;
    *(uint4*)&g_wbl[layer * 32768 + o * 256 + k0] = lo;
}

// ================= edge aggregation =========================================
__device__ __forceinline__ void red_add_v4(float* p, float4 v) {
    asm volatile("red.global.add.v4.f32 [%0], {%1,%2,%3,%4};"
                 :: "l"(p), "f"(v.x), "f"(v.y), "f"(v.z), "f"(v.w) : "memory");
}
__global__ void aggregate(const float* __restrict__ x, int sel) {
    int t = blockIdx.x * blockDim.x + threadIdx.x;
    int e = t >> 5, lane = t & 31;
    if (e >= N_EDGES) return;
    const float* src = (sel == 0) ? x : (sel == 1 ? g_h1 : g_h2);
    int s = g_src[e], d = g_dst[e];
    float4 v = ((const float4*)(src + s * D))[lane];
    red_add_v4(g_agg + d * D + lane * 4, v);
}

// ================= split-bf16 mma.sync SAGE-layer GEMM ======================
// Y[m,o] = relu( [mean(m)|hin(m)](K=256) . B[o](K=256) + bias[o] )
// acc += Ah*Bh + Ah*Bl + Al*Bh  (fp32 accum, lo*lo dropped: ~2^-18 rel)
// CTA tile 128x128, 8 warps (4m x 2n), warp tile 32x64, BK=32.
#define SMSTRIDE 40   // 32 bf16 + 8 pad (80B rows: conflict-free ldmatrix)

__global__ __launch_bounds__(256, 2) void gemm_mma(const float* __restrict__ xin,
                                                   int in_sel, int out_sel, int layer,
                                                   const float* __restrict__ bias) {
    __shared__ __align__(16) __nv_bfloat16 sAh[128 * SMSTRIDE];
    __shared__ __align__(16) __nv_bfloat16 sAl[128 * SMSTRIDE];
    __shared__ __align__(16) __nv_bfloat16 sBh[128 * SMSTRIDE];
    __shared__ __align__(16) __nv_bfloat16 sBl[128 * SMSTRIDE];

    const float* hin = (in_sel == 0) ? xin : (in_sel == 1 ? g_h1 : g_h2);
    float* hout = (out_sel == 1) ? g_h1 : g_h2;
    const __nv_bfloat16* wbh = g_wbh + layer * 32768;
    const __nv_bfloat16* wbl = g_wbl + layer * 32768;

    int tid = threadIdx.x;
    int lane = tid & 31, warp = tid >> 5;
    int wm = warp & 3, wn = warp >> 2;       // warp grid 4(m) x 2(n)
    int m0 = blockIdx.x * 128;

    uint32_t bAh = smem_u32(sAh), bAl = smem_u32(sAl);
    uint32_t bBh = smem_u32(sBh), bBl = smem_u32(sBl);

    float acc[2][8][4];
#pragma unroll
    for (int mt = 0; mt < 2; mt++)
#pragma unroll
        for (int nt = 0; nt < 8; nt++)
#pragma unroll
            for (int q = 0; q < 4; q++) acc[mt][nt][q] = 0.f;

    // ldmatrix source addresses (byte offsets computed per k-step below)
    int a_tile = lane >> 3, a_r = lane & 7;
    int a_row = wm * 32 + (a_tile & 1) * 8 + a_r;    // + mt*16
    int a_kof = (a_tile >> 1) * 8;                   // + k16
    int b_row = wn * 64 + (lane & 7);                // + nt*8
    int b_kof = ((lane >> 3) & 1) * 8;               // + k16 (lanes>=16 ignored by x2)

    for (int kc = 0; kc < 8; kc++) {
        // ---- fill A (split fp32 -> bf16 hi/lo, fold 1/deg into mean half) ----
        const float* Asrc = (kc < 4) ? g_agg : hin;
        int kloc = (kc & 3) * 32;
        int frow = tid >> 3, fkq = tid & 7;
#pragma unroll
        for (int it = 0; it < 4; it++) {
            int row = frow + it * 32;
            int m = m0 + row;
            float4 v = make_float4(0.f, 0.f, 0.f, 0.f);
            if (m < N_NODES) {
                v = *(const float4*)(Asrc + (size_t)m * 128 + kloc + fkq * 4);
                if (kc < 4) {
                    float s = g_inv[m];
                    v.x *= s; v.y *= s; v.z *= s; v.w *= s;
                }
            }
            uint2 hi, lo;
            hi.x = pack_hi(v.x, v.y, lo.x);
            hi.y = pack_hi(v.z, v.w, lo.y);
            *(uint2*)&sAh[row * SMSTRIDE + fkq * 4] = hi;
            *(uint2*)&sAl[row * SMSTRIDE + fkq * 4] = lo;
        }
        // ---- fill B (straight copy of pre-split planes) ----
#pragma unroll
        for (int it = 0; it < 2; it++) {
            int idx = tid + it * 256;        // 512 uint4 per plane
            int o = idx >> 2, q = idx & 3;
            *(uint4*)&sBh[o * SMSTRIDE + q * 8] = *(const uint4*)(wbh + o * 256 + kc * 32 + q * 8);
            *(uint4*)&sBl[o * SMSTRIDE + q * 8] = *(const uint4*)(wbl + o * 256 + kc * 32 + q * 8);
        }
        __syncthreads();

        // ---- 2 k16 steps ----
#pragma unroll
        for (int ks = 0; ks < 2; ks++) {
            int k16 = ks * 16;
            uint32_t ah[2][4], al[2][4];
#pragma unroll
            for (int mt = 0; mt < 2; mt++) {
                uint32_t off = (uint32_t)((a_row + mt * 16) * SMSTRIDE + k16 + a_kof) * 2;
                LDSM_X4(ah[mt], bAh + off);
                LDSM_X4(al[mt], bAl + off);
            }
#pragma unroll
            for (int nt = 0; nt < 8; nt++) {
                uint32_t bh[2], bl[2];
                uint32_t off = (uint32_t)((b_row + nt * 8) * SMSTRIDE + k16 + b_kof) * 2;
                LDSM_X2(bh, bBh + off);
                LDSM_X2(bl, bBl + off);
#pragma unroll
                for (int mt = 0; mt < 2; mt++) {
                    MMA_BF16(acc[mt][nt], ah[mt], bh);
                    MMA_BF16(acc[mt][nt], ah[mt], bl);
                    MMA_BF16(acc[mt][nt], al[mt], bh);
                }
            }
        }
        __syncthreads();
    }

    // ---- epilogue: bias + relu + store ----
    int g4 = lane >> 2, q4 = lane & 3;
    float bv[8][2];
#pragma unroll
    for (int nt = 0; nt < 8; nt++) {
        int n = wn * 64 + nt * 8 + q4 * 2;
        bv[nt][0] = __ldg(&bias[n]);
        bv[nt][1] = __ldg(&bias[n + 1]);
    }
#pragma unroll
    for (int mt = 0; mt < 2; mt++) {
#pragma unroll
        for (int h = 0; h < 2; h++) {
            int m = m0 + wm * 32 + mt * 16 + g4 + h * 8;
            if (m < N_NODES) {
#pragma unroll
                for (int nt = 0; nt < 8; nt++) {
                    int n = wn * 64 + nt * 8 + q4 * 2;
                    float2 o;
                    o.x = fmaxf(acc[mt][nt][h * 2 + 0] + bv[nt][0], 0.f);
                    o.y = fmaxf(acc[mt][nt][h * 2 + 1] + bv[nt][1], 0.f);
                    *(float2*)(hout + (size_t)m * 128 + n) = o;
                }
            }
        }
    }
}

// ================= pool + head ==============================================
__global__ void pool(const int* __restrict__ batch) {
    int t = blockIdx.x * blockDim.x + threadIdx.x;
    int n = t >> 5, lane = t & 31;
    if (n >= N_NODES) return;
    int g = min(max(batch[n], 0), NGRAPH - 1);
    float4 v = ((const float4*)(g_h1 + n * D))[lane];
    red_add_v4(g_gsum + g * D + lane * 4, v);
}

__global__ void finalk(const float* __restrict__ wlin, const float* __restrict__ blin,
                       float* __restrict__ out) {
    int g = blockIdx.x;
    __shared__ float row[128];
    int t = threadIdx.x;
    float inv = 1.f / fmaxf(g_gcnt[g], 1.f);
    row[t] = g_gsum[g * 128 + t] * inv;
    __syncthreads();
    if (t < DOUT) {
        float acc = blin[t];
#pragma unroll 4
        for (int k = 0; k < 128; k++) acc += row[k] * wlin[t * 128 + k];
        out[g * DOUT + t] = acc;
    }
}

// ================= launch ====================================================
extern "C" void kernel_launch(void* const* d_in, const int* in_sizes, int n_in,
                              void* d_out, int out_size) {
    const float* x     = (const float*)d_in[0];
    const int*   ei    = (const int*)d_in[1];
    const int*   batch = (const int*)d_in[2];
    const float* w1l = (const float*)d_in[3];
    const float* b1  = (const float*)d_in[4];
    const float* w1r = (const float*)d_in[5];
    const float* w2l = (const float*)d_in[6];
    const float* b2  = (const float*)d_in[7];
    const float* w2r = (const float*)d_in[8];
    const float* w3l = (const float*)d_in[9];
    const float* b3  = (const float*)d_in[10];
    const float* w3r = (const float*)d_in[11];
    const float* wlin = (const float*)d_in[12];
    const float* blin = (const float*)d_in[13];
    float* out = (float*)d_out;

    zero_small<<<196, 256>>>();
    prep_edges<<<(N_EDGES + 255) / 256, 256>>>(ei);
    prep_nodes<<<(N_NODES + 255) / 256, 256>>>(batch);
    build_wplanes<<<16, 256>>>(w1l, w1r, 0);
    build_wplanes<<<16, 256>>>(w2l, w2r, 1);
    build_wplanes<<<16, 256>>>(w3l, w3r, 2);

    const int AGG_BLOCKS = (N_EDGES * 32) / 256;
    const int ZA_BLOCKS  = (N_NODES * D / 4) / 256;
    const int GEMM_BLOCKS = (N_NODES + 127) / 128;

    zero_agg<<<ZA_BLOCKS, 256>>>();
    aggregate<<<AGG_BLOCKS, 256>>>(x, 0);
    gemm_mma<<<GEMM_BLOCKS, 256>>>(x, 0, 1, 0, b1);

    zero_agg<<<ZA_BLOCKS, 256>>>();
    aggregate<<<AGG_BLOCKS, 256>>>(x, 1);
    gemm_mma<<<GEMM_BLOCKS, 256>>>(x, 1, 2, 1, b2);

    zero_agg<<<ZA_BLOCKS, 256>>>();
    aggregate<<<AGG_BLOCKS, 256>>>(x, 2);
    gemm_mma<<<GEMM_BLOCKS, 256>>>(x, 2, 1, 2, b3);

    pool<<<(N_NODES * 32) / 256, 256>>>(batch);
    finalk<<<NGRAPH, 128>>>(wlin, blin, out);
}

// round 9
// speedup vs baseline: 1.7141x; 1.3047x over previous
#include <cuda_runtime.h>
#include <cuda_bf16.h>
#include <cstdint>

#define N_NODES 50000
#define N_EDGES 600000
#define D 128
#define NGRAPH 64
#define DOUT 16
#define SCAN_CHUNK 512
#define SCAN_BLKS ((N_NODES + SCAN_CHUNK - 1) / SCAN_CHUNK)   // 98

// ================= device scratch (no allocation allowed) ====================
__device__ __align__(128) float g_agg[N_NODES * D];   // mean-aggregated neighbors
__device__ __align__(128) float g_h1[N_NODES * D];
__device__ __align__(128) float g_h2[N_NODES * D];
__device__ float g_gcnt[NGRAPH];
__device__ __align__(128) float g_gsum[NGRAPH * D];
__device__ int g_degi[N_NODES];
__device__ int g_rowptr[N_NODES + 1];
__device__ int g_cursor[N_NODES];
__device__ int g_bsum[SCAN_BLKS];
__device__ int g_adj[N_EDGES];
// split-bf16 weight planes: [layer][o=128][k=256], k-contiguous
__device__ __align__(128) __nv_bfloat16 g_wbh[3 * 32768];
__device__ __align__(128) __nv_bfloat16 g_wbl[3 * 32768];

// ================= helpers ===================================================
__device__ __forceinline__ uint32_t smem_u32(const void* p) {
    uint32_t a;
    asm("{ .reg .u64 t; cvta.to.shared.u64 t, %1; cvt.u32.u64 %0, t; }" : "=r"(a) : "l"(p));
    return a;
}
__device__ __forceinline__ uint32_t pack_hi(float a, float b, uint32_t& lo) {
    __nv_bfloat16 ah = __float2bfloat16(a), bh = __float2bfloat16(b);
    __nv_bfloat16 al = __float2bfloat16(a - __bfloat162float(ah));
    __nv_bfloat16 bl = __float2bfloat16(b - __bfloat162float(bh));
    lo = ((uint32_t)__bfloat16_as_ushort(bl) << 16) | __bfloat16_as_ushort(al);
    return ((uint32_t)__bfloat16_as_ushort(bh) << 16) | __bfloat16_as_ushort(ah);
}
#define LDSM_X4(R, A) \
    asm volatile("ldmatrix.sync.aligned.m8n8.x4.shared.b16 {%0,%1,%2,%3}, [%4];" \
                 : "=r"((R)[0]), "=r"((R)[1]), "=r"((R)[2]), "=r"((R)[3]) : "r"(A))
#define LDSM_X2(R, A) \
    asm volatile("ldmatrix.sync.aligned.m8n8.x2.shared.b16 {%0,%1}, [%2];" \
                 : "=r"((R)[0]), "=r"((R)[1]) : "r"(A))
#define MMA_BF16(C, A, B) \
    asm volatile("mma.sync.aligned.m16n8k16.row.col.f32.bf16.bf16.f32 " \
                 "{%0,%1,%2,%3}, {%4,%5,%6,%7}, {%8,%9}, {%0,%1,%2,%3};" \
                 : "+f"((C)[0]), "+f"((C)[1]), "+f"((C)[2]), "+f"((C)[3]) \
                 : "r"((A)[0]), "r"((A)[1]), "r"((A)[2]), "r"((A)[3]), "r"((B)[0]), "r"((B)[1]))
__device__ __forceinline__ void red_add_v4(float* p, float4 v) {
    asm volatile("red.global.add.v4.f32 [%0], {%1,%2,%3,%4};"
                 :: "l"(p), "f"(v.x), "f"(v.y), "f"(v.z), "f"(v.w) : "memory");
}

// ================= prep: zero + CSR build ===================================
__global__ void zero_small() {
    int i = blockIdx.x * blockDim.x + threadIdx.x;
    if (i < N_NODES) g_degi[i] = 0;
    if (i < NGRAPH * D) g_gsum[i] = 0.f;
    if (i < NGRAPH) g_gcnt[i] = 0.f;
}
__global__ void count_deg(const int* __restrict__ ei) {
    int e = blockIdx.x * blockDim.x + threadIdx.x;
    if (e >= N_EDGES) return;
    int d = min(max(ei[N_EDGES + e], 0), N_NODES - 1);
    atomicAdd(&g_degi[d], 1);
}
__global__ void scan1() {
    __shared__ int s[SCAN_CHUNK];
    int b = blockIdx.x, t = threadIdx.x;
    int i = b * SCAN_CHUNK + t;
    int v = (i < N_NODES) ? g_degi[i] : 0;
    s[t] = v;
    __syncthreads();
#pragma unroll
    for (int off = 1; off < SCAN_CHUNK; off <<= 1) {
        int add = (t >= off) ? s[t - off] : 0;
        __syncthreads();
        s[t] += add;
        __syncthreads();
    }
    if (i < N_NODES) g_rowptr[i] = s[t] - v;   // exclusive
    if (t == SCAN_CHUNK - 1) g_bsum[b] = s[t];
}
__global__ void scan2() {
    if (threadIdx.x == 0) {
        int acc = 0;
        for (int b = 0; b < SCAN_BLKS; b++) { int v = g_bsum[b]; g_bsum[b] = acc; acc += v; }
        g_rowptr[N_NODES] = acc;
    }
}
__global__ void scan3() {
    int i = blockIdx.x * blockDim.x + threadIdx.x;
    if (i >= N_NODES) return;
    int r = g_rowptr[i] + g_bsum[i / SCAN_CHUNK];
    g_rowptr[i] = r;
    g_cursor[i] = r;
}
__global__ void fill_adj(const int* __restrict__ ei) {
    int e = blockIdx.x * blockDim.x + threadIdx.x;
    if (e >= N_EDGES) return;
    int s = min(max(ei[e], 0), N_NODES - 1);
    int d = min(max(ei[N_EDGES + e], 0), N_NODES - 1);
    int pos = atomicAdd(&g_cursor[d], 1);
    g_adj[pos] = s;
}
__global__ void prep_nodes(const int* __restrict__ batch) {
    int n = blockIdx.x * blockDim.x + threadIdx.x;
    if (n >= N_NODES) return;
    atomicAdd(&g_gcnt[min(max(batch[n], 0), NGRAPH - 1)], 1.f);
}
// all 3 layers in one launch: grid (16, 3)
__global__ void build_wplanes(const float* __restrict__ w1l, const float* __restrict__ w1r,
                              const float* __restrict__ w2l, const float* __restrict__ w2r,
                              const float* __restrict__ w3l, const float* __restrict__ w3r) {
    int layer = blockIdx.y;
    const float* wl = (layer == 0) ? w1l : (layer == 1) ? w2l : w3l;
    const float* wr = (layer == 0) ? w1r : (layer == 1) ? w2r : w3r;
    int i = blockIdx.x * blockDim.x + threadIdx.x;
    if (i >= 4096) return;
    int o = i >> 5, k0 = (i & 31) * 8;
    const float* src = (k0 < 128) ? (wl + o * 128 + k0) : (wr + o * 128 + (k0 - 128));
    float4 v0 = ((const float4*)src)[0], v1 = ((const float4*)src)[1];
    uint4 hi, lo;
    hi.x = pack_hi(v0.x, v0.y, lo.x);
    hi.y = pack_hi(v0.z, v0.w, lo.y);
    hi.z = pack_hi(v1.x, v1.y, lo.z);
    hi.w = pack_hi(v1.z, v1.w, lo.w);
    *(uint4*)&g_wbh[layer * 32768 + o * 256 + k0] = hi;
    *(uint4*)&g_wbl[layer * 32768 + o * 256 + k0] = lo;
}

// ================= gather aggregation (no atomics, writes mean) =============
__global__ __launch_bounds__(256) void gather_agg(const float* __restrict__ x, int sel) {
    int t = blockIdx.x * blockDim.x + threadIdx.x;
    int n = t >> 5, lane = t & 31;
    if (n >= N_NODES) return;
    const float* src = (sel == 0) ? x : (sel == 1 ? g_h1 : g_h2);
    int beg = g_rowptr[n], end = g_rowptr[n + 1];
    float4 a0 = make_float4(0.f, 0.f, 0.f, 0.f);
    float4 a1 = make_float4(0.f, 0.f, 0.f, 0.f);
    for (int base = beg; base < end; base += 32) {
        int idx = base + lane;
        int sv = (idx < end) ? g_adj[idx] : 0;
        int cnt = min(32, end - base);
        int j = 0;
        for (; j + 1 < cnt; j += 2) {
            int s0 = __shfl_sync(0xffffffffu, sv, j);
            int s1 = __shfl_sync(0xffffffffu, sv, j + 1);
            float4 v0 = ((const float4*)(src + (size_t)s0 * D))[lane];
            float4 v1 = ((const float4*)(src + (size_t)s1 * D))[lane];
            a0.x += v0.x; a0.y += v0.y; a0.z += v0.z; a0.w += v0.w;
            a1.x += v1.x; a1.y += v1.y; a1.z += v1.z; a1.w += v1.w;
        }
        if (j < cnt) {
            int s0 = __shfl_sync(0xffffffffu, sv, j);
            float4 v0 = ((const float4*)(src + (size_t)s0 * D))[lane];
            a0.x += v0.x; a0.y += v0.y; a0.z += v0.z; a0.w += v0.w;
        }
    }
    float inv = 1.f / fmaxf((float)(end - beg), 1.f);
    float4 o;
    o.x = (a0.x + a1.x) * inv;
    o.y = (a0.y + a1.y) * inv;
    o.z = (a0.z + a1.z) * inv;
    o.w = (a0.w + a1.w) * inv;
    ((float4*)(g_agg + (size_t)n * D))[lane] = o;
}

// ================= split-bf16 mma.sync SAGE-layer GEMM ======================
// Y[m,o] = relu( [mean(m)|hin(m)](K=256) . B[o](K=256) + bias[o] )
#define SMSTRIDE 40

__global__ __launch_bounds__(256, 2) void gemm_mma(const float* __restrict__ xin,
                                                   int in_sel, int out_sel, int layer,
                                                   const float* __restrict__ bias) {
    __shared__ __align__(16) __nv_bfloat16 sAh[128 * SMSTRIDE];
    __shared__ __align__(16) __nv_bfloat16 sAl[128 * SMSTRIDE];
    __shared__ __align__(16) __nv_bfloat16 sBh[128 * SMSTRIDE];
    __shared__ __align__(16) __nv_bfloat16 sBl[128 * SMSTRIDE];

    const float* hin = (in_sel == 0) ? xin : (in_sel == 1 ? g_h1 : g_h2);
    float* hout = (out_sel == 1) ? g_h1 : g_h2;
    const __nv_bfloat16* wbh = g_wbh + layer * 32768;
    const __nv_bfloat16* wbl = g_wbl + layer * 32768;

    int tid = threadIdx.x;
    int lane = tid & 31, warp = tid >> 5;
    int wm = warp & 3, wn = warp >> 2;
    int m0 = blockIdx.x * 128;

    uint32_t bAh = smem_u32(sAh), bAl = smem_u32(sAl);
    uint32_t bBh = smem_u32(sBh), bBl = smem_u32(sBl);

    float acc[2][8][4];
#pragma unroll
    for (int mt = 0; mt < 2; mt++)
#pragma unroll
        for (int nt = 0; nt < 8; nt++)
#pragma unroll
            for (int q = 0; q < 4; q++) acc[mt][nt][q] = 0.f;

    int a_tile = lane >> 3, a_r = lane & 7;
    int a_row = wm * 32 + (a_tile & 1) * 8 + a_r;
    int a_kof = (a_tile >> 1) * 8;
    int b_row = wn * 64 + (lane & 7);
    int b_kof = ((lane >> 3) & 1) * 8;

    for (int kc = 0; kc < 8; kc++) {
        const float* Asrc = (kc < 4) ? g_agg : hin;
        int kloc = (kc & 3) * 32;
        int frow = tid >> 3, fkq = tid & 7;
#pragma unroll
        for (int it = 0; it < 4; it++) {
            int row = frow + it * 32;
            int m = m0 + row;
            float4 v = make_float4(0.f, 0.f, 0.f, 0.f);
            if (m < N_NODES)
                v = *(const float4*)(Asrc + (size_t)m * 128 + kloc + fkq * 4);
            uint2 hi, lo;
            hi.x = pack_hi(v.x, v.y, lo.x);
            hi.y = pack_hi(v.z, v.w, lo.y);
            *(uint2*)&sAh[row * SMSTRIDE + fkq * 4] = hi;
            *(uint2*)&sAl[row * SMSTRIDE + fkq * 4] = lo;
        }
#pragma unroll
        for (int it = 0; it < 2; it++) {
            int idx = tid + it * 256;
            int o = idx >> 2, q = idx & 3;
            *(uint4*)&sBh[o * SMSTRIDE + q * 8] = *(const uint4*)(wbh + o * 256 + kc * 32 + q * 8);
            *(uint4*)&sBl[o * SMSTRIDE + q * 8] = *(const uint4*)(wbl + o * 256 + kc * 32 + q * 8);
        }
        __syncthreads();

#pragma unroll
        for (int ks = 0; ks < 2; ks++) {
            int k16 = ks * 16;
            uint32_t ah[2][4], al[2][4];
#pragma unroll
            for (int mt = 0; mt < 2; mt++) {
                uint32_t off = (uint32_t)((a_row + mt * 16) * SMSTRIDE + k16 + a_kof) * 2;
                LDSM_X4(ah[mt], bAh + off);
                LDSM_X4(al[mt], bAl + off);
            }
#pragma unroll
            for (int nt = 0; nt < 8; nt++) {
                uint32_t bh[2], bl[2];
                uint32_t off = (uint32_t)((b_row + nt * 8) * SMSTRIDE + k16 + b_kof) * 2;
                LDSM_X2(bh, bBh + off);
                LDSM_X2(bl, bBl + off);
#pragma unroll
                for (int mt = 0; mt < 2; mt++) {
                    MMA_BF16(acc[mt][nt], ah[mt], bh);
                    MMA_BF16(acc[mt][nt], ah[mt], bl);
                    MMA_BF16(acc[mt][nt], al[mt], bh);
                }
            }
        }
        __syncthreads();
    }

    int g4 = lane >> 2, q4 = lane & 3;
    float bv[8][2];
#pragma unroll
    for (int nt = 0; nt < 8; nt++) {
        int n = wn * 64 + nt * 8 + q4 * 2;
        bv[nt][0] = __ldg(&bias[n]);
        bv[nt][1] = __ldg(&bias[n + 1]);
    }
#pragma unroll
    for (int mt = 0; mt < 2; mt++) {
#pragma unroll
        for (int h = 0; h < 2; h++) {
            int m = m0 + wm * 32 + mt * 16 + g4 + h * 8;
            if (m < N_NODES) {
#pragma unroll
                for (int nt = 0; nt < 8; nt++) {
                    int n = wn * 64 + nt * 8 + q4 * 2;
                    float2 o;
                    o.x = fmaxf(acc[mt][nt][h * 2 + 0] + bv[nt][0], 0.f);
                    o.y = fmaxf(acc[mt][nt][h * 2 + 1] + bv[nt][1], 0.f);
                    *(float2*)(hout + (size_t)m * 128 + n) = o;
                }
            }
        }
    }
}

// ================= pool + head ==============================================
__global__ void pool(const int* __restrict__ batch) {
    int t = blockIdx.x * blockDim.x + threadIdx.x;
    int n = t >> 5, lane = t & 31;
    if (n >= N_NODES) return;
    int g = min(max(batch[n], 0), NGRAPH - 1);
    float4 v = ((const float4*)(g_h1 + (size_t)n * D))[lane];
    red_add_v4(g_gsum + g * D + lane * 4, v);
}
__global__ void finalk(const float* __restrict__ wlin, const float* __restrict__ blin,
                       float* __restrict__ out) {
    int g = blockIdx.x;
    __shared__ float row[128];
    int t = threadIdx.x;
    float inv = 1.f / fmaxf(g_gcnt[g], 1.f);
    row[t] = g_gsum[g * 128 + t] * inv;
    __syncthreads();
    if (t < DOUT) {
        float acc = blin[t];
#pragma unroll 4
        for (int k = 0; k < 128; k++) acc += row[k] * wlin[t * 128 + k];
        out[g * DOUT + t] = acc;
    }
}

// ================= launch ====================================================
extern "C" void kernel_launch(void* const* d_in, const int* in_sizes, int n_in,
                              void* d_out, int out_size) {
    const float* x     = (const float*)d_in[0];
    const int*   ei    = (const int*)d_in[1];
    const int*   batch = (const int*)d_in[2];
    const float* w1l = (const float*)d_in[3];
    const float* b1  = (const float*)d_in[4];
    const float* w1r = (const float*)d_in[5];
    const float* w2l = (const float*)d_in[6];
    const float* b2  = (const float*)d_in[7];
    const float* w2r = (const float*)d_in[8];
    const float* w3l = (const float*)d_in[9];
    const float* b3  = (const float*)d_in[10];
    const float* w3r = (const float*)d_in[11];
    const float* wlin = (const float*)d_in[12];
    const float* blin = (const float*)d_in[13];
    float* out = (float*)d_out;

    zero_small<<<196, 256>>>();
    count_deg<<<(N_EDGES + 255) / 256, 256>>>(ei);
    scan1<<<SCAN_BLKS, SCAN_CHUNK>>>();
    scan2<<<1, 32>>>();
    scan3<<<SCAN_BLKS, SCAN_CHUNK>>>();
    fill_adj<<<(N_EDGES + 255) / 256, 256>>>(ei);
    prep_nodes<<<(N_NODES + 255) / 256, 256>>>(batch);
    build_wplanes<<<dim3(16, 3), 256>>>(w1l, w1r, w2l, w2r, w3l, w3r);

    const int AGG_BLOCKS = (N_NODES * 32 + 255) / 256;   // 1 warp/node
    const int GEMM_BLOCKS = (N_NODES + 127) / 128;

    gather_agg<<<AGG_BLOCKS, 256>>>(x, 0);
    gemm_mma<<<GEMM_BLOCKS, 256>>>(x, 0, 1, 0, b1);

    gather_agg<<<AGG_BLOCKS, 256>>>(x, 1);
    gemm_mma<<<GEMM_BLOCKS, 256>>>(x, 1, 2, 1, b2);

    gather_agg<<<AGG_BLOCKS, 256>>>(x, 2);
    gemm_mma<<<GEMM_BLOCKS, 256>>>(x, 2, 1, 2, b3);

    pool<<<(N_NODES * 32 + 255) / 256, 256>>>(batch);
    finalk<<<NGRAPH, 128>>>(wlin, blin, out);
}

// round 12
// speedup vs baseline: 1.9293x; 1.1255x over previous
#include <cuda_runtime.h>
#include <cuda_bf16.h>
#include <cstdint>

#define N_NODES 50000
#define N_EDGES 600000
#define D 128
#define NGRAPH 64
#define DOUT 16
#define SCAN_CHUNK 512
#define SCAN_BLKS ((N_NODES + SCAN_CHUNK - 1) / SCAN_CHUNK)   // 98

// ================= device scratch (no allocation allowed) ====================
__device__ __align__(128) float g_agg[N_NODES * D];
__device__ __align__(128) float g_h1[N_NODES * D];
__device__ __align__(128) float g_h2[N_NODES * D];
__device__ float g_gcnt[NGRAPH];
__device__ __align__(128) float g_gsum[NGRAPH * D];
__device__ int g_degi[N_NODES];
__device__ int g_rowptr[N_NODES + 1];
__device__ int g_cursor[N_NODES];
__device__ int g_bsum[SCAN_BLKS];
__device__ int g_adj[N_EDGES];
__device__ __align__(128) __nv_bfloat16 g_wbh[3 * 32768];
__device__ __align__(128) __nv_bfloat16 g_wbl[3 * 32768];

// ================= helpers ===================================================
__device__ __forceinline__ uint32_t smem_u32(const void* p) {
    uint32_t a;
    asm("{ .reg .u64 t; cvta.to.shared.u64 t, %1; cvt.u32.u64 %0, t; }" : "=r"(a) : "l"(p));
    return a;
}
__device__ __forceinline__ uint32_t pack_hi(float a, float b, uint32_t& lo) {
    __nv_bfloat16 ah = __float2bfloat16(a), bh = __float2bfloat16(b);
    __nv_bfloat16 al = __float2bfloat16(a - __bfloat162float(ah));
    __nv_bfloat16 bl = __float2bfloat16(b - __bfloat162float(bh));
    lo = ((uint32_t)__bfloat16_as_ushort(bl) << 16) | __bfloat16_as_ushort(al);
    return ((uint32_t)__bfloat16_as_ushort(bh) << 16) | __bfloat16_as_ushort(ah);
}
#define LDSM_X4(R, A) \
    asm volatile("ldmatrix.sync.aligned.m8n8.x4.shared.b16 {%0,%1,%2,%3}, [%4];" \
                 : "=r"((R)[0]), "=r"((R)[1]), "=r"((R)[2]), "=r"((R)[3]) : "r"(A))
#define LDSM_X2(R, A) \
    asm volatile("ldmatrix.sync.aligned.m8n8.x2.shared.b16 {%0,%1}, [%2];" \
                 : "=r"((R)[0]), "=r"((R)[1]) : "r"(A))
#define MMA_BF16(C, A, B) \
    asm volatile("mma.sync.aligned.m16n8k16.row.col.f32.bf16.bf16.f32 " \
                 "{%0,%1,%2,%3}, {%4,%5,%6,%7}, {%8,%9}, {%0,%1,%2,%3};" \
                 : "+f"((C)[0]), "+f"((C)[1]), "+f"((C)[2]), "+f"((C)[3]) \
                 : "r"((A)[0]), "r"((A)[1]), "r"((A)[2]), "r"((A)[3]), "r"((B)[0]), "r"((B)[1]))
__device__ __forceinline__ void red_add_v4(float* p, float4 v) {
    asm volatile("red.global.add.v4.f32 [%0], {%1,%2,%3,%4};"
                 :: "l"(p), "f"(v.x), "f"(v.y), "f"(v.z), "f"(v.w) : "memory");
}

// ================= prep: zero + CSR build ===================================
__global__ void zero_small() {
    int i = blockIdx.x * blockDim.x + threadIdx.x;
    if (i < N_NODES) g_degi[i] = 0;
    if (i < NGRAPH * D) g_gsum[i] = 0.f;
    if (i < NGRAPH) g_gcnt[i] = 0.f;
    if (i == 0) g_rowptr[N_NODES] = N_EDGES;   // total degree is a constant
}
__global__ void count_deg(const int* __restrict__ ei) {
    int e = blockIdx.x * blockDim.x + threadIdx.x;
    if (e >= N_EDGES) return;
    int d = min(max(ei[N_EDGES + e], 0), N_NODES - 1);
    atomicAdd(&g_degi[d], 1);
}
__global__ void scan1() {
    __shared__ int s[SCAN_CHUNK];
    int b = blockIdx.x, t = threadIdx.x;
    int i = b * SCAN_CHUNK + t;
    int v = (i < N_NODES) ? g_degi[i] : 0;
    s[t] = v;
    __syncthreads();
#pragma unroll
    for (int off = 1; off < SCAN_CHUNK; off <<= 1) {
        int add = (t >= off) ? s[t - off] : 0;
        __syncthreads();
        s[t] += add;
        __syncthreads();
    }
    if (i < N_NODES) g_rowptr[i] = s[t] - v;   // exclusive within block
    if (t == SCAN_CHUNK - 1) g_bsum[b] = s[t];
}
// add-back: each block computes its prefix from g_bsum locally; also counts gcnt
__global__ void scan3(const int* __restrict__ batch) {
    __shared__ int sb[SCAN_BLKS];
    __shared__ int spre;
    int b = blockIdx.x, t = threadIdx.x;
    if (t < SCAN_BLKS) sb[t] = g_bsum[t];
    __syncthreads();
    if (t == 0) {
        int acc = 0;
        for (int j = 0; j < b; j++) acc += sb[j];
        spre = acc;
    }
    __syncthreads();
    int i = b * SCAN_CHUNK + t;
    if (i < N_NODES) {
        int r = g_rowptr[i] + spre;
        g_rowptr[i] = r;
        g_cursor[i] = r;
        atomicAdd(&g_gcnt[min(max(batch[i], 0), NGRAPH - 1)], 1.f);
    }
}
__global__ void fill_adj(const int* __restrict__ ei) {
    int e = blockIdx.x * blockDim.x + threadIdx.x;
    if (e >= N_EDGES) return;
    int s = min(max(ei[e], 0), N_NODES - 1);
    int d = min(max(ei[N_EDGES + e], 0), N_NODES - 1);
    int pos = atomicAdd(&g_cursor[d], 1);
    g_adj[pos] = s;
}
__global__ void build_wplanes(const float* __restrict__ w1l, const float* __restrict__ w1r,
                              const float* __restrict__ w2l, const float* __restrict__ w2r,
                              const float* __restrict__ w3l, const float* __restrict__ w3r) {
    int layer = blockIdx.y;
    const float* wl = (layer == 0) ? w1l : (layer == 1) ? w2l : w3l;
    const float* wr = (layer == 0) ? w1r : (layer == 1) ? w2r : w3r;
    int i = blockIdx.x * blockDim.x + threadIdx.x;
    if (i >= 4096) return;
    int o = i >> 5, k0 = (i & 31) * 8;
    const float* src = (k0 < 128) ? (wl + o * 128 + k0) : (wr + o * 128 + (k0 - 128));
    float4 v0 = ((const float4*)src)[0], v1 = ((const float4*)src)[1];
    uint4 hi, lo;
    hi.x = pack_hi(v0.x, v0.y, lo.x);
    hi.y = pack_hi(v0.z, v0.w, lo.y);
    hi.z = pack_hi(v1.x, v1.y, lo.z);
    hi.w = pack_hi(v1.z, v1.w, lo.w);
    *(uint4*)&g_wbh[layer * 32768 + o * 256 + k0] = hi;
    *(uint4*)&g_wbl[layer * 32768 + o * 256 + k0] = lo;
}

// ================= gather aggregation (no atomics, writes mean) =============
__global__ __launch_bounds__(256) void gather_agg(const float* __restrict__ x, int sel) {
    int t = blockIdx.x * blockDim.x + threadIdx.x;
    int n = t >> 5, lane = t & 31;
    if (n >= N_NODES) return;
    const float* src = (sel == 0) ? x : (sel == 1 ? g_h1 : g_h2);
    int beg = g_rowptr[n], end = g_rowptr[n + 1];
    float4 a0 = make_float4(0.f, 0.f, 0.f, 0.f);
    float4 a1 = make_float4(0.f, 0.f, 0.f, 0.f);
    for (int base = beg; base < end; base += 32) {
        int idx = base + lane;
        int sv = (idx < end) ? g_adj[idx] : 0;
        int cnt = min(32, end - base);
        int j = 0;
        for (; j + 1 < cnt; j += 2) {
            int s0 = __shfl_sync(0xffffffffu, sv, j);
            int s1 = __shfl_sync(0xffffffffu, sv, j + 1);
            float4 v0 = ((const float4*)(src + (size_t)s0 * D))[lane];
            float4 v1 = ((const float4*)(src + (size_t)s1 * D))[lane];
            a0.x += v0.x; a0.y += v0.y; a0.z += v0.z; a0.w += v0.w;
            a1.x += v1.x; a1.y += v1.y; a1.z += v1.z; a1.w += v1.w;
        }
        if (j < cnt) {
            int s0 = __shfl_sync(0xffffffffu, sv, j);
            float4 v0 = ((const float4*)(src + (size_t)s0 * D))[lane];
            a0.x += v0.x; a0.y += v0.y; a0.z += v0.z; a0.w += v0.w;
        }
    }
    float inv = 1.f / fmaxf((float)(end - beg), 1.f);
    float4 o;
    o.x = (a0.x + a1.x) * inv;
    o.y = (a0.y + a1.y) * inv;
    o.z = (a0.z + a1.z) * inv;
    o.w = (a0.w + a1.w) * inv;
    ((float4*)(g_agg + (size_t)n * D))[lane] = o;
}

// ================= split-bf16 mma.sync SAGE-layer GEMM ======================
// M=64 CTA tile, 128 threads (4 warps: 2m x 2n), warp tile 32x64, BK=32.
#define SMSTRIDE 40

__global__ __launch_bounds__(128, 4) void gemm_mma(const float* __restrict__ xin,
                                                   int in_sel, int out_sel, int layer,
                                                   const float* __restrict__ bias) {
    __shared__ __align__(16) __nv_bfloat16 sAh[64 * SMSTRIDE];
    __shared__ __align__(16) __nv_bfloat16 sAl[64 * SMSTRIDE];
    __shared__ __align__(16) __nv_bfloat16 sBh[128 * SMSTRIDE];
    __shared__ __align__(16) __nv_bfloat16 sBl[128 * SMSTRIDE];

    const float* hin = (in_sel == 0) ? xin : (in_sel == 1 ? g_h1 : g_h2);
    float* hout = (out_sel == 1) ? g_h1 : g_h2;
    const __nv_bfloat16* wbh = g_wbh + layer * 32768;
    const __nv_bfloat16* wbl = g_wbl + layer * 32768;

    int tid = threadIdx.x;
    int lane = tid & 31, warp = tid >> 5;
    int wm = warp & 1, wn = warp >> 1;       // warp grid 2(m) x 2(n)
    int m0 = blockIdx.x * 64;

    uint32_t bAh = smem_u32(sAh), bAl = smem_u32(sAl);
    uint32_t bBh = smem_u32(sBh), bBl = smem_u32(sBl);

    float acc[2][8][4];
#pragma unroll
    for (int mt = 0; mt < 2; mt++)
#pragma unroll
        for (int nt = 0; nt < 8; nt++)
#pragma unroll
            for (int q = 0; q < 4; q++) acc[mt][nt][q] = 0.f;

    int a_tile = lane >> 3, a_r = lane & 7;
    int a_row = wm * 32 + (a_tile & 1) * 8 + a_r;
    int a_kof = (a_tile >> 1) * 8;
    int b_row = wn * 64 + (lane & 7);
    int b_kof = ((lane >> 3) & 1) * 8;

    for (int kc = 0; kc < 8; kc++) {
        const float* Asrc = (kc < 4) ? g_agg : hin;
        int kloc = (kc & 3) * 32;
        // ---- fill A: 64 rows x 32 k fp32 -> split bf16; 512 float4, 128 thr x4 ----
#pragma unroll
        for (int it = 0; it < 4; it++) {
            int idx = tid + it * 128;
            int row = idx >> 3, kq = idx & 7;
            int m = m0 + row;
            float4 v = make_float4(0.f, 0.f, 0.f, 0.f);
            if (m < N_NODES)
                v = *(const float4*)(Asrc + (size_t)m * 128 + kloc + kq * 4);
            uint2 hi, lo;
            hi.x = pack_hi(v.x, v.y, lo.x);
            hi.y = pack_hi(v.z, v.w, lo.y);
            *(uint2*)&sAh[row * SMSTRIDE + kq * 4] = hi;
            *(uint2*)&sAl[row * SMSTRIDE + kq * 4] = lo;
        }
        // ---- fill B: 128 o x 32 k bf16 planes; 512 uint4 per plane, x4 each ----
#pragma unroll
        for (int it = 0; it < 4; it++) {
            int idx = tid + it * 128;
            int o = idx >> 2, q = idx & 3;
            *(uint4*)&sBh[o * SMSTRIDE + q * 8] = *(const uint4*)(wbh + o * 256 + kc * 32 + q * 8);
            *(uint4*)&sBl[o * SMSTRIDE + q * 8] = *(const uint4*)(wbl + o * 256 + kc * 32 + q * 8);
        }
        __syncthreads();

#pragma unroll
        for (int ks = 0; ks < 2; ks++) {
            int k16 = ks * 16;
            uint32_t ah[2][4], al[2][4];
#pragma unroll
            for (int mt = 0; mt < 2; mt++) {
                uint32_t off = (uint32_t)((a_row + mt * 16) * SMSTRIDE + k16 + a_kof) * 2;
                LDSM_X4(ah[mt], bAh + off);
                LDSM_X4(al[mt], bAl + off);
            }
#pragma unroll
            for (int nt = 0; nt < 8; nt++) {
                uint32_t bh[2], bl[2];
                uint32_t off = (uint32_t)((b_row + nt * 8) * SMSTRIDE + k16 + b_kof) * 2;
                LDSM_X2(bh, bBh + off);
                LDSM_X2(bl, bBl + off);
#pragma unroll
                for (int mt = 0; mt < 2; mt++) {
                    MMA_BF16(acc[mt][nt], ah[mt], bh);
                    MMA_BF16(acc[mt][nt], ah[mt], bl);
                    MMA_BF16(acc[mt][nt], al[mt], bh);
                }
            }
        }
        __syncthreads();
    }

    int g4 = lane >> 2, q4 = lane & 3;
    float bv[8][2];
#pragma unroll
    for (int nt = 0; nt < 8; nt++) {
        int n = wn * 64 + nt * 8 + q4 * 2;
        bv[nt][0] = __ldg(&bias[n]);
        bv[nt][1] = __ldg(&bias[n + 1]);
    }
#pragma unroll
    for (int mt = 0; mt < 2; mt++) {
#pragma unroll
        for (int h = 0; h < 2; h++) {
            int m = m0 + wm * 32 + mt * 16 + g4 + h * 8;
            if (m < N_NODES) {
#pragma unroll
                for (int nt = 0; nt < 8; nt++) {
                    int n = wn * 64 + nt * 8 + q4 * 2;
                    float2 o;
                    o.x = fmaxf(acc[mt][nt][h * 2 + 0] + bv[nt][0], 0.f);
                    o.y = fmaxf(acc[mt][nt][h * 2 + 1] + bv[nt][1], 0.f);
                    *(float2*)(hout + (size_t)m * 128 + n) = o;
                }
            }
        }
    }
}

// ================= pool (segment-accumulated) + head ========================
// batch is sorted: accumulate runs in registers, red once per segment per warp.
__global__ __launch_bounds__(256) void pool2(const int* __restrict__ batch) {
    int warp = threadIdx.x >> 5, lane = threadIdx.x & 31;
    int nb = blockIdx.x * 256;
    float4 acc = make_float4(0.f, 0.f, 0.f, 0.f);
    int cur = -1;
    for (int j = warp; j < 256; j += 8) {
        int n = nb + j;
        if (n >= N_NODES) break;
        int g = min(max(batch[n], 0), NGRAPH - 1);
        float4 v = ((const float4*)(g_h1 + (size_t)n * D))[lane];
        if (g != cur) {
            if (cur >= 0) red_add_v4(g_gsum + cur * D + lane * 4, acc);
            cur = g;
            acc = v;
        } else {
            acc.x += v.x; acc.y += v.y; acc.z += v.z; acc.w += v.w;
        }
    }
    if (cur >= 0) red_add_v4(g_gsum + cur * D + lane * 4, acc);
}
__global__ void finalk(const float* __restrict__ wlin, const float* __restrict__ blin,
                       float* __restrict__ out) {
    int g = blockIdx.x;
    __shared__ float row[128];
    int t = threadIdx.x;
    float inv = 1.f / fmaxf(g_gcnt[g], 1.f);
    row[t] = g_gsum[g * 128 + t] * inv;
    __syncthreads();
    if (t < DOUT) {
        float acc = blin[t];
#pragma unroll 4
        for (int k = 0; k < 128; k++) acc += row[k] * wlin[t * 128 + k];
        out[g * DOUT + t] = acc;
    }
}

// ================= launch ====================================================
extern "C" void kernel_launch(void* const* d_in, const int* in_sizes, int n_in,
                              void* d_out, int out_size) {
    const float* x     = (const float*)d_in[0];
    const int*   ei    = (const int*)d_in[1];
    const int*   batch = (const int*)d_in[2];
    const float* w1l = (const float*)d_in[3];
    const float* b1  = (const float*)d_in[4];
    const float* w1r = (const float*)d_in[5];
    const float* w2l = (const float*)d_in[6];
    const float* b2  = (const float*)d_in[7];
    const float* w2r = (const float*)d_in[8];
    const float* w3l = (const float*)d_in[9];
    const float* b3  = (const float*)d_in[10];
    const float* w3r = (const float*)d_in[11];
    const float* wlin = (const float*)d_in[12];
    const float* blin = (const float*)d_in[13];
    float* out = (float*)d_out;

    zero_small<<<196, 256>>>();
    count_deg<<<(N_EDGES + 255) / 256, 256>>>(ei);
    scan1<<<SCAN_BLKS, SCAN_CHUNK>>>();
    scan3<<<SCAN_BLKS, SCAN_CHUNK>>>(batch);
    fill_adj<<<(N_EDGES + 255) / 256, 256>>>(ei);
    build_wplanes<<<dim3(16, 3), 256>>>(w1l, w1r, w2l, w2r, w3l, w3r);

    const int AGG_BLOCKS = (N_NODES * 32 + 255) / 256;   // 1 warp/node
    const int GEMM_BLOCKS = (N_NODES + 63) / 64;         // 782 M=64 tiles

    gather_agg<<<AGG_BLOCKS, 256>>>(x, 0);
    gemm_mma<<<GEMM_BLOCKS, 128>>>(x, 0, 1, 0, b1);

    gather_agg<<<AGG_BLOCKS, 256>>>(x, 1);
    gemm_mma<<<GEMM_BLOCKS, 128>>>(x, 1, 2, 1, b2);

    gather_agg<<<AGG_BLOCKS, 256>>>(x, 2);
    gemm_mma<<<GEMM_BLOCKS, 128>>>(x, 2, 1, 2, b3);

    pool2<<<(N_NODES + 255) / 256, 256>>>(batch);
    finalk<<<NGRAPH, 128>>>(wlin, blin, out);
}

// round 13
// speedup vs baseline: 2.1912x; 1.1358x over previous
#include <cuda_runtime.h>
#include <cuda_bf16.h>
#include <cstdint>

#define N_NODES 50000
#define N_EDGES 600000
#define D 128
#define NGRAPH 64
#define DOUT 16
#define SCAN_CHUNK 512
#define SCAN_BLKS ((N_NODES + SCAN_CHUNK - 1) / SCAN_CHUNK)   // 98

// ================= device scratch (no allocation allowed) ====================
__device__ __align__(128) float g_agg[N_NODES * D];
__device__ __align__(128) float g_h1[N_NODES * D];
__device__ __align__(128) float g_h2[N_NODES * D];
__device__ float g_gcnt[NGRAPH];
__device__ __align__(128) float g_gsum[NGRAPH * D];
__device__ int g_degi[N_NODES];
__device__ int g_rowptr[N_NODES + 1];
__device__ int g_cursor[N_NODES];
__device__ int g_bsum[SCAN_BLKS];
__device__ int g_adj[N_EDGES];
__device__ __align__(128) __nv_bfloat16 g_wbh[3 * 32768];
__device__ __align__(128) __nv_bfloat16 g_wbl[3 * 32768];

// ================= helpers ===================================================
__device__ __forceinline__ uint32_t smem_u32(const void* p) {
    uint32_t a;
    asm("{ .reg .u64 t; cvta.to.shared.u64 t, %1; cvt.u32.u64 %0, t; }" : "=r"(a) : "l"(p));
    return a;
}
__device__ __forceinline__ uint32_t pack_hi(float a, float b, uint32_t& lo) {
    __nv_bfloat16 ah = __float2bfloat16(a), bh = __float2bfloat16(b);
    __nv_bfloat16 al = __float2bfloat16(a - __bfloat162float(ah));
    __nv_bfloat16 bl = __float2bfloat16(b - __bfloat162float(bh));
    lo = ((uint32_t)__bfloat16_as_ushort(bl) << 16) | __bfloat16_as_ushort(al);
    return ((uint32_t)__bfloat16_as_ushort(bh) << 16) | __bfloat16_as_ushort(ah);
}
#define LDSM_X4(R, A) \
    asm volatile("ldmatrix.sync.aligned.m8n8.x4.shared.b16 {%0,%1,%2,%3}, [%4];" \
                 : "=r"((R)[0]), "=r"((R)[1]), "=r"((R)[2]), "=r"((R)[3]) : "r"(A))
#define LDSM_X2(R, A) \
    asm volatile("ldmatrix.sync.aligned.m8n8.x2.shared.b16 {%0,%1}, [%2];" \
                 : "=r"((R)[0]), "=r"((R)[1]) : "r"(A))
#define MMA_BF16(C, A, B) \
    asm volatile("mma.sync.aligned.m16n8k16.row.col.f32.bf16.bf16.f32 " \
                 "{%0,%1,%2,%3}, {%4,%5,%6,%7}, {%8,%9}, {%0,%1,%2,%3};" \
                 : "+f"((C)[0]), "+f"((C)[1]), "+f"((C)[2]), "+f"((C)[3]) \
                 : "r"((A)[0]), "r"((A)[1]), "r"((A)[2]), "r"((A)[3]), "r"((B)[0]), "r"((B)[1]))
__device__ __forceinline__ void red_add_v4(float* p, float4 v) {
    asm volatile("red.global.add.v4.f32 [%0], {%1,%2,%3,%4};"
                 :: "l"(p), "f"(v.x), "f"(v.y), "f"(v.z), "f"(v.w) : "memory");
}

// ================= prep: zero + CSR build ===================================
__global__ void zero_small() {
    int i = blockIdx.x * blockDim.x + threadIdx.x;
    if (i < N_NODES) g_degi[i] = 0;
    if (i < NGRAPH * D) g_gsum[i] = 0.f;
    if (i < NGRAPH) g_gcnt[i] = 0.f;
    if (i == 0) g_rowptr[N_NODES] = N_EDGES;   // total degree is a constant
}
__global__ void count_deg(const int* __restrict__ ei) {
    int e = blockIdx.x * blockDim.x + threadIdx.x;
    if (e >= N_EDGES) return;
    int d = min(max(ei[N_EDGES + e], 0), N_NODES - 1);
    atomicAdd(&g_degi[d], 1);
}
__global__ void scan1() {
    __shared__ int s[SCAN_CHUNK];
    int b = blockIdx.x, t = threadIdx.x;
    int i = b * SCAN_CHUNK + t;
    int v = (i < N_NODES) ? g_degi[i] : 0;
    s[t] = v;
    __syncthreads();
#pragma unroll
    for (int off = 1; off < SCAN_CHUNK; off <<= 1) {
        int add = (t >= off) ? s[t - off] : 0;
        __syncthreads();
        s[t] += add;
        __syncthreads();
    }
    if (i < N_NODES) g_rowptr[i] = s[t] - v;   // exclusive within block
    if (t == SCAN_CHUNK - 1) g_bsum[b] = s[t];
}
// add-back: each block computes its prefix from g_bsum locally (pure scan now)
__global__ void scan3() {
    __shared__ int sb[SCAN_BLKS];
    __shared__ int spre;
    int b = blockIdx.x, t = threadIdx.x;
    if (t < SCAN_BLKS) sb[t] = g_bsum[t];
    __syncthreads();
    if (t == 0) {
        int acc = 0;
        for (int j = 0; j < b; j++) acc += sb[j];
        spre = acc;
    }
    __syncthreads();
    int i = b * SCAN_CHUNK + t;
    if (i < N_NODES) {
        int r = g_rowptr[i] + spre;
        g_rowptr[i] = r;
        g_cursor[i] = r;
    }
}
__global__ void fill_adj(const int* __restrict__ ei) {
    int e = blockIdx.x * blockDim.x + threadIdx.x;
    if (e >= N_EDGES) return;
    int s = min(max(ei[e], 0), N_NODES - 1);
    int d = min(max(ei[N_EDGES + e], 0), N_NODES - 1);
    int pos = atomicAdd(&g_cursor[d], 1);
    g_adj[pos] = s;
}
__global__ void build_wplanes(const float* __restrict__ w1l, const float* __restrict__ w1r,
                              const float* __restrict__ w2l, const float* __restrict__ w2r,
                              const float* __restrict__ w3l, const float* __restrict__ w3r) {
    int layer = blockIdx.y;
    const float* wl = (layer == 0) ? w1l : (layer == 1) ? w2l : w3l;
    const float* wr = (layer == 0) ? w1r : (layer == 1) ? w2r : w3r;
    int i = blockIdx.x * blockDim.x + threadIdx.x;
    if (i >= 4096) return;
    int o = i >> 5, k0 = (i & 31) * 8;
    const float* src = (k0 < 128) ? (wl + o * 128 + k0) : (wr + o * 128 + (k0 - 128));
    float4 v0 = ((const float4*)src)[0], v1 = ((const float4*)src)[1];
    uint4 hi, lo;
    hi.x = pack_hi(v0.x, v0.y, lo.x);
    hi.y = pack_hi(v0.z, v0.w, lo.y);
    hi.z = pack_hi(v1.x, v1.y, lo.z);
    hi.w = pack_hi(v1.z, v1.w, lo.w);
    *(uint4*)&g_wbh[layer * 32768 + o * 256 + k0] = hi;
    *(uint4*)&g_wbl[layer * 32768 + o * 256 + k0] = lo;
}

// ================= gather aggregation (no atomics, writes mean) =============
__global__ __launch_bounds__(256) void gather_agg(const float* __restrict__ x, int sel) {
    int t = blockIdx.x * blockDim.x + threadIdx.x;
    int n = t >> 5, lane = t & 31;
    if (n >= N_NODES) return;
    const float* src = (sel == 0) ? x : (sel == 1 ? g_h1 : g_h2);
    int beg = g_rowptr[n], end = g_rowptr[n + 1];
    float4 a0 = make_float4(0.f, 0.f, 0.f, 0.f);
    float4 a1 = make_float4(0.f, 0.f, 0.f, 0.f);
    for (int base = beg; base < end; base += 32) {
        int idx = base + lane;
        int sv = (idx < end) ? g_adj[idx] : 0;
        int cnt = min(32, end - base);
        int j = 0;
        for (; j + 1 < cnt; j += 2) {
            int s0 = __shfl_sync(0xffffffffu, sv, j);
            int s1 = __shfl_sync(0xffffffffu, sv, j + 1);
            float4 v0 = ((const float4*)(src + (size_t)s0 * D))[lane];
            float4 v1 = ((const float4*)(src + (size_t)s1 * D))[lane];
            a0.x += v0.x; a0.y += v0.y; a0.z += v0.z; a0.w += v0.w;
            a1.x += v1.x; a1.y += v1.y; a1.z += v1.z; a1.w += v1.w;
        }
        if (j < cnt) {
            int s0 = __shfl_sync(0xffffffffu, sv, j);
            float4 v0 = ((const float4*)(src + (size_t)s0 * D))[lane];
            a0.x += v0.x; a0.y += v0.y; a0.z += v0.z; a0.w += v0.w;
        }
    }
    float inv = 1.f / fmaxf((float)(end - beg), 1.f);
    float4 o;
    o.x = (a0.x + a1.x) * inv;
    o.y = (a0.y + a1.y) * inv;
    o.z = (a0.z + a1.z) * inv;
    o.w = (a0.w + a1.w) * inv;
    ((float4*)(g_agg + (size_t)n * D))[lane] = o;
}

// ================= split-bf16 mma.sync SAGE-layer GEMM ======================
// M=64 CTA tile, 128 threads (4 warps: 2m x 2n), warp tile 32x64, BK=32.
#define SMSTRIDE 40

__global__ __launch_bounds__(128, 4) void gemm_mma(const float* __restrict__ xin,
                                                   int in_sel, int out_sel, int layer,
                                                   const float* __restrict__ bias) {
    __shared__ __align__(16) __nv_bfloat16 sAh[64 * SMSTRIDE];
    __shared__ __align__(16) __nv_bfloat16 sAl[64 * SMSTRIDE];
    __shared__ __align__(16) __nv_bfloat16 sBh[128 * SMSTRIDE];
    __shared__ __align__(16) __nv_bfloat16 sBl[128 * SMSTRIDE];

    const float* hin = (in_sel == 0) ? xin : (in_sel == 1 ? g_h1 : g_h2);
    float* hout = (out_sel == 1) ? g_h1 : g_h2;
    const __nv_bfloat16* wbh = g_wbh + layer * 32768;
    const __nv_bfloat16* wbl = g_wbl + layer * 32768;

    int tid = threadIdx.x;
    int lane = tid & 31, warp = tid >> 5;
    int wm = warp & 1, wn = warp >> 1;       // warp grid 2(m) x 2(n)
    int m0 = blockIdx.x * 64;

    uint32_t bAh = smem_u32(sAh), bAl = smem_u32(sAl);
    uint32_t bBh = smem_u32(sBh), bBl = smem_u32(sBl);

    float acc[2][8][4];
#pragma unroll
    for (int mt = 0; mt < 2; mt++)
#pragma unroll
        for (int nt = 0; nt < 8; nt++)
#pragma unroll
            for (int q = 0; q < 4; q++) acc[mt][nt][q] = 0.f;

    int a_tile = lane >> 3, a_r = lane & 7;
    int a_row = wm * 32 + (a_tile & 1) * 8 + a_r;
    int a_kof = (a_tile >> 1) * 8;
    int b_row = wn * 64 + (lane & 7);
    int b_kof = ((lane >> 3) & 1) * 8;

    for (int kc = 0; kc < 8; kc++) {
        const float* Asrc = (kc < 4) ? g_agg : hin;
        int kloc = (kc & 3) * 32;
        // ---- fill A: 64 rows x 32 k fp32 -> split bf16; 512 float4, 128 thr x4 ----
#pragma unroll
        for (int it = 0; it < 4; it++) {
            int idx = tid + it * 128;
            int row = idx >> 3, kq = idx & 7;
            int m = m0 + row;
            float4 v = make_float4(0.f, 0.f, 0.f, 0.f);
            if (m < N_NODES)
                v = *(const float4*)(Asrc + (size_t)m * 128 + kloc + kq * 4);
            uint2 hi, lo;
            hi.x = pack_hi(v.x, v.y, lo.x);
            hi.y = pack_hi(v.z, v.w, lo.y);
            *(uint2*)&sAh[row * SMSTRIDE + kq * 4] = hi;
            *(uint2*)&sAl[row * SMSTRIDE + kq * 4] = lo;
        }
        // ---- fill B: 128 o x 32 k bf16 planes; 512 uint4 per plane, x4 each ----
#pragma unroll
        for (int it = 0; it < 4; it++) {
            int idx = tid + it * 128;
            int o = idx >> 2, q = idx & 3;
            *(uint4*)&sBh[o * SMSTRIDE + q * 8] = *(const uint4*)(wbh + o * 256 + kc * 32 + q * 8);
            *(uint4*)&sBl[o * SMSTRIDE + q * 8] = *(const uint4*)(wbl + o * 256 + kc * 32 + q * 8);
        }
        __syncthreads();

#pragma unroll
        for (int ks = 0; ks < 2; ks++) {
            int k16 = ks * 16;
            uint32_t ah[2][4], al[2][4];
#pragma unroll
            for (int mt = 0; mt < 2; mt++) {
                uint32_t off = (uint32_t)((a_row + mt * 16) * SMSTRIDE + k16 + a_kof) * 2;
                LDSM_X4(ah[mt], bAh + off);
                LDSM_X4(al[mt], bAl + off);
            }
#pragma unroll
            for (int nt = 0; nt < 8; nt++) {
                uint32_t bh[2], bl[2];
                uint32_t off = (uint32_t)((b_row + nt * 8) * SMSTRIDE + k16 + b_kof) * 2;
                LDSM_X2(bh, bBh + off);
                LDSM_X2(bl, bBl + off);
#pragma unroll
                for (int mt = 0; mt < 2; mt++) {
                    MMA_BF16(acc[mt][nt], ah[mt], bh);
                    MMA_BF16(acc[mt][nt], ah[mt], bl);
                    MMA_BF16(acc[mt][nt], al[mt], bh);
                }
            }
        }
        __syncthreads();
    }

    int g4 = lane >> 2, q4 = lane & 3;
    float bv[8][2];
#pragma unroll
    for (int nt = 0; nt < 8; nt++) {
        int n = wn * 64 + nt * 8 + q4 * 2;
        bv[nt][0] = __ldg(&bias[n]);
        bv[nt][1] = __ldg(&bias[n + 1]);
    }
#pragma unroll
    for (int mt = 0; mt < 2; mt++) {
#pragma unroll
        for (int h = 0; h < 2; h++) {
            int m = m0 + wm * 32 + mt * 16 + g4 + h * 8;
            if (m < N_NODES) {
#pragma unroll
                for (int nt = 0; nt < 8; nt++) {
                    int n = wn * 64 + nt * 8 + q4 * 2;
                    float2 o;
                    o.x = fmaxf(acc[mt][nt][h * 2 + 0] + bv[nt][0], 0.f);
                    o.y = fmaxf(acc[mt][nt][h * 2 + 1] + bv[nt][1], 0.f);
                    *(float2*)(hout + (size_t)m * 128 + n) = o;
                }
            }
        }
    }
}

// ================= pool (segment-accumulated, also counts gcnt) =============
// batch is sorted: accumulate runs in registers, one red per segment per warp.
__global__ __launch_bounds__(256) void pool2(const int* __restrict__ batch) {
    int warp = threadIdx.x >> 5, lane = threadIdx.x & 31;
    int nb = blockIdx.x * 256;
    float4 acc = make_float4(0.f, 0.f, 0.f, 0.f);
    int cur = -1, cnt = 0;
    for (int j = warp; j < 256; j += 8) {
        int n = nb + j;
        if (n >= N_NODES) break;
        int g = min(max(batch[n], 0), NGRAPH - 1);
        float4 v = ((const float4*)(g_h1 + (size_t)n * D))[lane];
        if (g != cur) {
            if (cur >= 0) {
                red_add_v4(g_gsum + cur * D + lane * 4, acc);
                if (lane == 0) atomicAdd(&g_gcnt[cur], (float)cnt);
            }
            cur = g;
            acc = v;
            cnt = 1;
        } else {
            acc.x += v.x; acc.y += v.y; acc.z += v.z; acc.w += v.w;
            cnt++;
        }
    }
    if (cur >= 0) {
        red_add_v4(g_gsum + cur * D + lane * 4, acc);
        if (lane == 0) atomicAdd(&g_gcnt[cur], (float)cnt);
    }
}
__global__ void finalk(const float* __restrict__ wlin, const float* __restrict__ blin,
                       float* __restrict__ out) {
    int g = blockIdx.x;
    __shared__ float row[128];
    int t = threadIdx.x;
    float inv = 1.f / fmaxf(g_gcnt[g], 1.f);
    row[t] = g_gsum[g * 128 + t] * inv;
    __syncthreads();
    if (t < DOUT) {
        float acc = blin[t];
#pragma unroll 4
        for (int k = 0; k < 128; k++) acc += row[k] * wlin[t * 128 + k];
        out[g * DOUT + t] = acc;
    }
}

// ================= launch ====================================================
extern "C" void kernel_launch(void* const* d_in, const int* in_sizes, int n_in,
                              void* d_out, int out_size) {
    const float* x     = (const float*)d_in[0];
    const int*   ei    = (const int*)d_in[1];
    const int*   batch = (const int*)d_in[2];
    const float* w1l = (const float*)d_in[3];
    const float* b1  = (const float*)d_in[4];
    const float* w1r = (const float*)d_in[5];
    const float* w2l = (const float*)d_in[6];
    const float* b2  = (const float*)d_in[7];
    const float* w2r = (const float*)d_in[8];
    const float* w3l = (const float*)d_in[9];
    const float* b3  = (const float*)d_in[10];
    const float* w3r = (const float*)d_in[11];
    const float* wlin = (const float*)d_in[12];
    const float* blin = (const float*)d_in[13];
    float* out = (float*)d_out;

    zero_small<<<196, 256>>>();
    count_deg<<<(N_EDGES + 255) / 256, 256>>>(ei);
    scan1<<<SCAN_BLKS, SCAN_CHUNK>>>();
    scan3<<<SCAN_BLKS, SCAN_CHUNK>>>();
    fill_adj<<<(N_EDGES + 255) / 256, 256>>>(ei);
    build_wplanes<<<dim3(16, 3), 256>>>(w1l, w1r, w2l, w2r, w3l, w3r);

    const int AGG_BLOCKS = (N_NODES * 32 + 255) / 256;   // 1 warp/node
    const int GEMM_BLOCKS = (N_NODES + 63) / 64;         // 782 M=64 tiles

    gather_agg<<<AGG_BLOCKS, 256>>>(x, 0);
    gemm_mma<<<GEMM_BLOCKS, 128>>>(x, 0, 1, 0, b1);

    gather_agg<<<AGG_BLOCKS, 256>>>(x, 1);
    gemm_mma<<<GEMM_BLOCKS, 128>>>(x, 1, 2, 1, b2);

    gather_agg<<<AGG_BLOCKS, 256>>>(x, 2);
    gemm_mma<<<GEMM_BLOCKS, 128>>>(x, 2, 1, 2, b3);

    pool2<<<(N_NODES + 255) / 256, 256>>>(batch);
    finalk<<<NGRAPH, 128>>>(wlin, blin, out);
}

// round 14
// speedup vs baseline: 2.1929x; 1.0008x over previous
#include <cuda_runtime.h>
#include <cuda_bf16.h>
#include <cstdint>

#define N_NODES 50000
#define N_EDGES 600000
#define D 128
#define NGRAPH 64
#define DOUT 16
#define SCAN_CHUNK 512
#define SCAN_BLKS ((N_NODES + SCAN_CHUNK - 1) / SCAN_CHUNK)   // 98

// ================= device scratch (no allocation allowed) ====================
__device__ __align__(128) float g_agg[N_NODES * D];
__device__ __align__(128) float g_h1[N_NODES * D];
__device__ __align__(128) float g_h2[N_NODES * D];
__device__ float g_gcnt[NGRAPH];
__device__ __align__(128) float g_gsum[NGRAPH * D];
__device__ int g_degi[N_NODES];
__device__ int g_rowptr[N_NODES + 1];
__device__ int g_cursor[N_NODES];
__device__ int g_bsum[SCAN_BLKS];
__device__ int g_adj[N_EDGES];
__device__ __align__(128) __nv_bfloat16 g_wbh[3 * 32768];
__device__ __align__(128) __nv_bfloat16 g_wbl[3 * 32768];

// ================= helpers ===================================================
__device__ __forceinline__ uint32_t smem_u32(const void* p) {
    uint32_t a;
    asm("{ .reg .u64 t; cvta.to.shared.u64 t, %1; cvt.u32.u64 %0, t; }" : "=r"(a) : "l"(p));
    return a;
}
__device__ __forceinline__ uint32_t pack_hi(float a, float b, uint32_t& lo) {
    __nv_bfloat16 ah = __float2bfloat16(a), bh = __float2bfloat16(b);
    __nv_bfloat16 al = __float2bfloat16(a - __bfloat162float(ah));
    __nv_bfloat16 bl = __float2bfloat16(b - __bfloat162float(bh));
    lo = ((uint32_t)__bfloat16_as_ushort(bl) << 16) | __bfloat16_as_ushort(al);
    return ((uint32_t)__bfloat16_as_ushort(bh) << 16) | __bfloat16_as_ushort(ah);
}
#define LDSM_X4(R, A) \
    asm volatile("ldmatrix.sync.aligned.m8n8.x4.shared.b16 {%0,%1,%2,%3}, [%4];" \
                 : "=r"((R)[0]), "=r"((R)[1]), "=r"((R)[2]), "=r"((R)[3]) : "r"(A))
#define LDSM_X2(R, A) \
    asm volatile("ldmatrix.sync.aligned.m8n8.x2.shared.b16 {%0,%1}, [%2];" \
                 : "=r"((R)[0]), "=r"((R)[1]) : "r"(A))
#define MMA_BF16(C, A, B) \
    asm volatile("mma.sync.aligned.m16n8k16.row.col.f32.bf16.bf16.f32 " \
                 "{%0,%1,%2,%3}, {%4,%5,%6,%7}, {%8,%9}, {%0,%1,%2,%3};" \
                 : "+f"((C)[0]), "+f"((C)[1]), "+f"((C)[2]), "+f"((C)[3]) \
                 : "r"((A)[0]), "r"((A)[1]), "r"((A)[2]), "r"((A)[3]), "r"((B)[0]), "r"((B)[1]))
__device__ __forceinline__ void red_add_v4(float* p, float4 v) {
    asm volatile("red.global.add.v4.f32 [%0], {%1,%2,%3,%4};"
                 :: "l"(p), "f"(v.x), "f"(v.y), "f"(v.z), "f"(v.w) : "memory");
}

// ================= prep: zero + CSR build ===================================
__global__ void zero_small() {
    int i = blockIdx.x * blockDim.x + threadIdx.x;
    if (i < N_NODES) g_degi[i] = 0;
    if (i < NGRAPH * D) g_gsum[i] = 0.f;
    if (i < NGRAPH) g_gcnt[i] = 0.f;
    if (i == 0) g_rowptr[N_NODES] = N_EDGES;   // total degree is a constant
}
__global__ void count_deg(const int* __restrict__ ei) {
    int e = blockIdx.x * blockDim.x + threadIdx.x;
    if (e >= N_EDGES) return;
    int d = min(max(ei[N_EDGES + e], 0), N_NODES - 1);
    atomicAdd(&g_degi[d], 1);
}
__global__ void scan1() {
    __shared__ int s[SCAN_CHUNK];
    int b = blockIdx.x, t = threadIdx.x;
    int i = b * SCAN_CHUNK + t;
    int v = (i < N_NODES) ? g_degi[i] : 0;
    s[t] = v;
    __syncthreads();
#pragma unroll
    for (int off = 1; off < SCAN_CHUNK; off <<= 1) {
        int add = (t >= off) ? s[t - off] : 0;
        __syncthreads();
        s[t] += add;
        __syncthreads();
    }
    if (i < N_NODES) g_rowptr[i] = s[t] - v;   // exclusive within block
    if (t == SCAN_CHUNK - 1) g_bsum[b] = s[t];
}
// add-back: each block computes its prefix from g_bsum locally (pure scan now)
__global__ void scan3() {
    __shared__ int sb[SCAN_BLKS];
    __shared__ int spre;
    int b = blockIdx.x, t = threadIdx.x;
    if (t < SCAN_BLKS) sb[t] = g_bsum[t];
    __syncthreads();
    if (t == 0) {
        int acc = 0;
        for (int j = 0; j < b; j++) acc += sb[j];
        spre = acc;
    }
    __syncthreads();
    int i = b * SCAN_CHUNK + t;
    if (i < N_NODES) {
        int r = g_rowptr[i] + spre;
        g_rowptr[i] = r;
        g_cursor[i] = r;
    }
}
__global__ void fill_adj(const int* __restrict__ ei) {
    int e = blockIdx.x * blockDim.x + threadIdx.x;
    if (e >= N_EDGES) return;
    int s = min(max(ei[e], 0), N_NODES - 1);
    int d = min(max(ei[N_EDGES + e], 0), N_NODES - 1);
    int pos = atomicAdd(&g_cursor[d], 1);
    g_adj[pos] = s;
}
__global__ void build_wplanes(const float* __restrict__ w1l, const float* __restrict__ w1r,
                              const float* __restrict__ w2l, const float* __restrict__ w2r,
                              const float* __restrict__ w3l, const float* __restrict__ w3r) {
    int layer = blockIdx.y;
    const float* wl = (layer == 0) ? w1l : (layer == 1) ? w2l : w3l;
    const float* wr = (layer == 0) ? w1r : (layer == 1) ? w2r : w3r;
    int i = blockIdx.x * blockDim.x + threadIdx.x;
    if (i >= 4096) return;
    int o = i >> 5, k0 = (i & 31) * 8;
    const float* src = (k0 < 128) ? (wl + o * 128 + k0) : (wr + o * 128 + (k0 - 128));
    float4 v0 = ((const float4*)src)[0], v1 = ((const float4*)src)[1];
    uint4 hi, lo;
    hi.x = pack_hi(v0.x, v0.y, lo.x);
    hi.y = pack_hi(v0.z, v0.w, lo.y);
    hi.z = pack_hi(v1.x, v1.y, lo.z);
    hi.w = pack_hi(v1.z, v1.w, lo.w);
    *(uint4*)&g_wbh[layer * 32768 + o * 256 + k0] = hi;
    *(uint4*)&g_wbl[layer * 32768 + o * 256 + k0] = lo;
}

// ================= gather aggregation (no atomics, writes mean) =============
__global__ __launch_bounds__(256) void gather_agg(const float* __restrict__ x, int sel) {
    int t = blockIdx.x * blockDim.x + threadIdx.x;
    int n = t >> 5, lane = t & 31;
    if (n >= N_NODES) return;
    const float* src = (sel == 0) ? x : (sel == 1 ? g_h1 : g_h2);
    int beg = g_rowptr[n], end = g_rowptr[n + 1];
    float4 a0 = make_float4(0.f, 0.f, 0.f, 0.f);
    float4 a1 = make_float4(0.f, 0.f, 0.f, 0.f);
    for (int base = beg; base < end; base += 32) {
        int idx = base + lane;
        int sv = (idx < end) ? g_adj[idx] : 0;
        int cnt = min(32, end - base);
        int j = 0;
        for (; j + 1 < cnt; j += 2) {
            int s0 = __shfl_sync(0xffffffffu, sv, j);
            int s1 = __shfl_sync(0xffffffffu, sv, j + 1);
            float4 v0 = ((const float4*)(src + (size_t)s0 * D))[lane];
            float4 v1 = ((const float4*)(src + (size_t)s1 * D))[lane];
            a0.x += v0.x; a0.y += v0.y; a0.z += v0.z; a0.w += v0.w;
            a1.x += v1.x; a1.y += v1.y; a1.z += v1.z; a1.w += v1.w;
        }
        if (j < cnt) {
            int s0 = __shfl_sync(0xffffffffu, sv, j);
            float4 v0 = ((const float4*)(src + (size_t)s0 * D))[lane];
            a0.x += v0.x; a0.y += v0.y; a0.z += v0.z; a0.w += v0.w;
        }
    }
    float inv = 1.f / fmaxf((float)(end - beg), 1.f);
    float4 o;
    o.x = (a0.x + a1.x) * inv;
    o.y = (a0.y + a1.y) * inv;
    o.z = (a0.z + a1.z) * inv;
    o.w = (a0.w + a1.w) * inv;
    ((float4*)(g_agg + (size_t)n * D))[lane] = o;
}

// ================= split-bf16 mma.sync SAGE-layer GEMM ======================
// M=64 CTA tile, 128 threads (4 warps: 2m x 2n), warp tile 32x64, BK=32.
#define SMSTRIDE 40

__global__ __launch_bounds__(128, 4) void gemm_mma(const float* __restrict__ xin,
                                                   int in_sel, int out_sel, int layer,
                                                   const float* __restrict__ bias) {
    __shared__ __align__(16) __nv_bfloat16 sAh[64 * SMSTRIDE];
    __shared__ __align__(16) __nv_bfloat16 sAl[64 * SMSTRIDE];
    __shared__ __align__(16) __nv_bfloat16 sBh[128 * SMSTRIDE];
    __shared__ __align__(16) __nv_bfloat16 sBl[128 * SMSTRIDE];

    const float* hin = (in_sel == 0) ? xin : (in_sel == 1 ? g_h1 : g_h2);
    float* hout = (out_sel == 1) ? g_h1 : g_h2;
    const __nv_bfloat16* wbh = g_wbh + layer * 32768;
    const __nv_bfloat16* wbl = g_wbl + layer * 32768;

    int tid = threadIdx.x;
    int lane = tid & 31, warp = tid >> 5;
    int wm = warp & 1, wn = warp >> 1;       // warp grid 2(m) x 2(n)
    int m0 = blockIdx.x * 64;

    uint32_t bAh = smem_u32(sAh), bAl = smem_u32(sAl);
    uint32_t bBh = smem_u32(sBh), bBl = smem_u32(sBl);

    float acc[2][8][4];
#pragma unroll
    for (int mt = 0; mt < 2; mt++)
#pragma unroll
        for (int nt = 0; nt < 8; nt++)
#pragma unroll
            for (int q = 0; q < 4; q++) acc[mt][nt][q] = 0.f;

    int a_tile = lane >> 3, a_r = lane & 7;
    int a_row = wm * 32 + (a_tile & 1) * 8 + a_r;
    int a_kof = (a_tile >> 1) * 8;
    int b_row = wn * 64 + (lane & 7);
    int b_kof = ((lane >> 3) & 1) * 8;

    for (int kc = 0; kc < 8; kc++) {
        const float* Asrc = (kc < 4) ? g_agg : hin;
        int kloc = (kc & 3) * 32;
        // ---- fill A: 64 rows x 32 k fp32 -> split bf16; 512 float4, 128 thr x4 ----
#pragma unroll
        for (int it = 0; it < 4; it++) {
            int idx = tid + it * 128;
            int row = idx >> 3, kq = idx & 7;
            int m = m0 + row;
            float4 v = make_float4(0.f, 0.f, 0.f, 0.f);
            if (m < N_NODES)
                v = *(const float4*)(Asrc + (size_t)m * 128 + kloc + kq * 4);
            uint2 hi, lo;
            hi.x = pack_hi(v.x, v.y, lo.x);
            hi.y = pack_hi(v.z, v.w, lo.y);
            *(uint2*)&sAh[row * SMSTRIDE + kq * 4] = hi;
            *(uint2*)&sAl[row * SMSTRIDE + kq * 4] = lo;
        }
        // ---- fill B: 128 o x 32 k bf16 planes; 512 uint4 per plane, x4 each ----
#pragma unroll
        for (int it = 0; it < 4; it++) {
            int idx = tid + it * 128;
            int o = idx >> 2, q = idx & 3;
            *(uint4*)&sBh[o * SMSTRIDE + q * 8] = *(const uint4*)(wbh + o * 256 + kc * 32 + q * 8);
            *(uint4*)&sBl[o * SMSTRIDE + q * 8] = *(const uint4*)(wbl + o * 256 + kc * 32 + q * 8);
        }
        __syncthreads();

#pragma unroll
        for (int ks = 0; ks < 2; ks++) {
            int k16 = ks * 16;
            uint32_t ah[2][4], al[2][4];
#pragma unroll
            for (int mt = 0; mt < 2; mt++) {
                uint32_t off = (uint32_t)((a_row + mt * 16) * SMSTRIDE + k16 + a_kof) * 2;
                LDSM_X4(ah[mt], bAh + off);
                LDSM_X4(al[mt], bAl + off);
            }
#pragma unroll
            for (int nt = 0; nt < 8; nt++) {
                uint32_t bh[2], bl[2];
                uint32_t off = (uint32_t)((b_row + nt * 8) * SMSTRIDE + k16 + b_kof) * 2;
                LDSM_X2(bh, bBh + off);
                LDSM_X2(bl, bBl + off);
#pragma unroll
                for (int mt = 0; mt < 2; mt++) {
                    MMA_BF16(acc[mt][nt], ah[mt], bh);
                    MMA_BF16(acc[mt][nt], ah[mt], bl);
                    MMA_BF16(acc[mt][nt], al[mt], bh);
                }
            }
        }
        __syncthreads();
    }

    int g4 = lane >> 2, q4 = lane & 3;
    float bv[8][2];
#pragma unroll
    for (int nt = 0; nt < 8; nt++) {
        int n = wn * 64 + nt * 8 + q4 * 2;
        bv[nt][0] = __ldg(&bias[n]);
        bv[nt][1] = __ldg(&bias[n + 1]);
    }
#pragma unroll
    for (int mt = 0; mt < 2; mt++) {
#pragma unroll
        for (int h = 0; h < 2; h++) {
            int m = m0 + wm * 32 + mt * 16 + g4 + h * 8;
            if (m < N_NODES) {
#pragma unroll
                for (int nt = 0; nt < 8; nt++) {
                    int n = wn * 64 + nt * 8 + q4 * 2;
                    float2 o;
                    o.x = fmaxf(acc[mt][nt][h * 2 + 0] + bv[nt][0], 0.f);
                    o.y = fmaxf(acc[mt][nt][h * 2 + 1] + bv[nt][1], 0.f);
                    *(float2*)(hout + (size_t)m * 128 + n) = o;
                }
            }
        }
    }
}

// ================= pool (segment-accumulated, also counts gcnt) =============
// batch is sorted: accumulate runs in registers, one red per segment per warp.
__global__ __launch_bounds__(256) void pool2(const int* __restrict__ batch) {
    int warp = threadIdx.x >> 5, lane = threadIdx.x & 31;
    int nb = blockIdx.x * 256;
    float4 acc = make_float4(0.f, 0.f, 0.f, 0.f);
    int cur = -1, cnt = 0;
    for (int j = warp; j < 256; j += 8) {
        int n = nb + j;
        if (n >= N_NODES) break;
        int g = min(max(batch[n], 0), NGRAPH - 1);
        float4 v = ((const float4*)(g_h1 + (size_t)n * D))[lane];
        if (g != cur) {
            if (cur >= 0) {
                red_add_v4(g_gsum + cur * D + lane * 4, acc);
                if (lane == 0) atomicAdd(&g_gcnt[cur], (float)cnt);
            }
            cur = g;
            acc = v;
            cnt = 1;
        } else {
            acc.x += v.x; acc.y += v.y; acc.z += v.z; acc.w += v.w;
            cnt++;
        }
    }
    if (cur >= 0) {
        red_add_v4(g_gsum + cur * D + lane * 4, acc);
        if (lane == 0) atomicAdd(&g_gcnt[cur], (float)cnt);
    }
}
__global__ void finalk(const float* __restrict__ wlin, const float* __restrict__ blin,
                       float* __restrict__ out) {
    int g = blockIdx.x;
    __shared__ float row[128];
    int t = threadIdx.x;
    float inv = 1.f / fmaxf(g_gcnt[g], 1.f);
    row[t] = g_gsum[g * 128 + t] * inv;
    __syncthreads();
    if (t < DOUT) {
        float acc = blin[t];
#pragma unroll 4
        for (int k = 0; k < 128; k++) acc += row[k] * wlin[t * 128 + k];
        out[g * DOUT + t] = acc;
    }
}

// ================= launch ====================================================
extern "C" void kernel_launch(void* const* d_in, const int* in_sizes, int n_in,
                              void* d_out, int out_size) {
    const float* x     = (const float*)d_in[0];
    const int*   ei    = (const int*)d_in[1];
    const int*   batch = (const int*)d_in[2];
    const float* w1l = (const float*)d_in[3];
    const float* b1  = (const float*)d_in[4];
    const float* w1r = (const float*)d_in[5];
    const float* w2l = (const float*)d_in[6];
    const float* b2  = (const float*)d_in[7];
    const float* w2r = (const float*)d_in[8];
    const float* w3l = (const float*)d_in[9];
    const float* b3  = (const float*)d_in[10];
    const float* w3r = (const float*)d_in[11];
    const float* wlin = (const float*)d_in[12];
    const float* blin = (const float*)d_in[13];
    float* out = (float*)d_out;

    zero_small<<<196, 256>>>();
    count_deg<<<(N_EDGES + 255) / 256, 256>>>(ei);
    scan1<<<SCAN_BLKS, SCAN_CHUNK>>>();
    scan3<<<SCAN_BLKS, SCAN_CHUNK>>>();
    fill_adj<<<(N_EDGES + 255) / 256, 256>>>(ei);
    build_wplanes<<<dim3(16, 3), 256>>>(w1l, w1r, w2l, w2r, w3l, w3r);

    const int AGG_BLOCKS = (N_NODES * 32 + 255) / 256;   // 1 warp/node
    const int GEMM_BLOCKS = (N_NODES + 63) / 64;         // 782 M=64 tiles

    gather_agg<<<AGG_BLOCKS, 256>>>(x, 0);
    gemm_mma<<<GEMM_BLOCKS, 128>>>(x, 0, 1, 0, b1);

    gather_agg<<<AGG_BLOCKS, 256>>>(x, 1);
    gemm_mma<<<GEMM_BLOCKS, 128>>>(x, 1, 2, 1, b2);

    gather_agg<<<AGG_BLOCKS, 256>>>(x, 2);
    gemm_mma<<<GEMM_BLOCKS, 128>>>(x, 2, 1, 2, b3);

    pool2<<<(N_NODES + 255) / 256, 256>>>(batch);
    finalk<<<NGRAPH, 128>>>(wlin, blin, out);
}